// round 6
// baseline (speedup 1.0000x reference)
#include <cuda_runtime.h>
#include <cuda_bf16.h>
#include <cstdint>
#include <math.h>

#define Bv   2
#define Sv   2048
#define Dv   1024
#define Hv   16
#define DKv  64
#define DFFv 4096
#define Mv   (Bv * Sv)   // 4096 rows

// ---------------- scratch (device globals; no allocation allowed) ----------
__device__ float g_x1[Mv * Dv];
__device__ float g_y[Mv * Dv];

__device__ __nv_bfloat16 g_xh[Mv * Dv],  g_xl[Mv * Dv];
__device__ __nv_bfloat16 g_qh[Mv * Dv],  g_ql[Mv * Dv];
__device__ __nv_bfloat16 g_kh[Mv * Dv],  g_kl[Mv * Dv];
__device__ __nv_bfloat16 g_vh[Mv * Dv],  g_vl[Mv * Dv];
__device__ __nv_bfloat16 g_ah[Mv * Dv],  g_al[Mv * Dv];
__device__ __nv_bfloat16 g_x1h[Mv * Dv], g_x1l[Mv * Dv];
__device__ __nv_bfloat16 g_hh[(size_t)Mv * DFFv], g_hl[(size_t)Mv * DFFv];

__device__ __nv_bfloat16 g_wqh[Dv * Dv], g_wql[Dv * Dv];
__device__ __nv_bfloat16 g_wkh[Dv * Dv], g_wkl[Dv * Dv];
__device__ __nv_bfloat16 g_wvh[Dv * Dv], g_wvl[Dv * Dv];
__device__ __nv_bfloat16 g_woh[Dv * Dv], g_wol[Dv * Dv];
__device__ __nv_bfloat16 g_w1h[Dv * DFFv], g_w1l[Dv * DFFv];   // transposed: [DFF, D]
__device__ __nv_bfloat16 g_w2h[Dv * DFFv], g_w2l[Dv * DFFv];   // transposed: [D, DFF]

// ---------------- PTX helpers (base sm_80+ only; no tcgen05) ----------------
static __device__ __forceinline__ uint32_t s2u(const void* p) {
    uint32_t a;
    asm("{ .reg .u64 t; cvta.to.shared.u64 t, %1; cvt.u32.u64 %0, t; }"
        : "=r"(a) : "l"(p));
    return a;
}

static __device__ __forceinline__ void ldsm4(uint32_t* r, uint32_t addr) {
    asm volatile("ldmatrix.sync.aligned.m8n8.x4.shared.b16 {%0,%1,%2,%3}, [%4];"
        : "=r"(r[0]), "=r"(r[1]), "=r"(r[2]), "=r"(r[3]) : "r"(addr));
}

static __device__ __forceinline__ void mma16816(
    float* d, const uint32_t* a, const uint32_t* b)
{
    asm volatile("mma.sync.aligned.m16n8k16.row.col.f32.bf16.bf16.f32 "
        "{%0,%1,%2,%3}, {%4,%5,%6,%7}, {%8,%9}, {%0,%1,%2,%3};"
        : "+f"(d[0]), "+f"(d[1]), "+f"(d[2]), "+f"(d[3])
        : "r"(a[0]), "r"(a[1]), "r"(a[2]), "r"(a[3]), "r"(b[0]), "r"(b[1]));
}

#define CP16(dst, src) \
    asm volatile("cp.async.cg.shared.global [%0], [%1], 16;" \
                 :: "r"(dst), "l"(src))
#define CP_COMMIT() asm volatile("cp.async.commit_group;" ::: "memory")
#define CP_WAIT0()  asm volatile("cp.async.wait_group 0;" ::: "memory")
#define CP_WAIT1()  asm volatile("cp.async.wait_group 1;" ::: "memory")

// ---------------- fast exp on FMA pipe: pexp(s) = exp(s / 8) ----------------
static __device__ __forceinline__ float pexp(float s) {
    const float C = 0.125f * 1.4426950408889634f;
    s = fmaxf(s, -500.0f);
    float yr = fmaf(s, C, 12582912.0f);
    int   n  = __float_as_int(yr) - 0x4B400000;
    float nf = yr - 12582912.0f;
    float f  = fmaf(s, C, -nf);
    float p  = 0.0018775767f;
    p = fmaf(p, f, 0.0089893397f);
    p = fmaf(p, f, 0.0558026980f);
    p = fmaf(p, f, 0.2401597153f);
    p = fmaf(p, f, 0.6931471825f);
    p = fmaf(p, f, 1.0f);
    return __int_as_float(__float_as_int(p) + (n << 23));
}

// ---------------- bf16 hi/lo split helpers ----------------------------------
static __device__ __forceinline__ void store_split4(
    __nv_bfloat16* __restrict__ hi, __nv_bfloat16* __restrict__ lo,
    size_t off, float4 v)
{
    __nv_bfloat16 h0 = __float2bfloat16(v.x), h1 = __float2bfloat16(v.y);
    __nv_bfloat16 h2 = __float2bfloat16(v.z), h3 = __float2bfloat16(v.w);
    __nv_bfloat16 l0 = __float2bfloat16(v.x - __bfloat162float(h0));
    __nv_bfloat16 l1 = __float2bfloat16(v.y - __bfloat162float(h1));
    __nv_bfloat16 l2 = __float2bfloat16(v.z - __bfloat162float(h2));
    __nv_bfloat16 l3 = __float2bfloat16(v.w - __bfloat162float(h3));
    __nv_bfloat162 ph0, ph1, pl0, pl1;
    ph0.x = h0; ph0.y = h1; ph1.x = h2; ph1.y = h3;
    pl0.x = l0; pl0.y = l1; pl1.x = l2; pl1.y = l3;
    uint2 uh, ul;
    uh.x = *reinterpret_cast<uint32_t*>(&ph0);
    uh.y = *reinterpret_cast<uint32_t*>(&ph1);
    ul.x = *reinterpret_cast<uint32_t*>(&pl0);
    ul.y = *reinterpret_cast<uint32_t*>(&pl1);
    *reinterpret_cast<uint2*>(hi + off) = uh;
    *reinterpret_cast<uint2*>(lo + off) = ul;
}

static __device__ __forceinline__ void store_split2(
    __nv_bfloat16* __restrict__ hi, __nv_bfloat16* __restrict__ lo,
    size_t off, float x, float y)
{
    __nv_bfloat16 h0 = __float2bfloat16(x), h1 = __float2bfloat16(y);
    __nv_bfloat162 ph, pl;
    ph.x = h0; ph.y = h1;
    pl.x = __float2bfloat16(x - __bfloat162float(h0));
    pl.y = __float2bfloat16(y - __bfloat162float(h1));
    *reinterpret_cast<__nv_bfloat162*>(hi + off) = ph;
    *reinterpret_cast<__nv_bfloat162*>(lo + off) = pl;
}

static __device__ __forceinline__ void psplit(
    float x, float y, uint32_t& hi, uint32_t& lo)
{
    __nv_bfloat162 h, l;
    h.x = __float2bfloat16(x); h.y = __float2bfloat16(y);
    l.x = __float2bfloat16(x - __bfloat162float(h.x));
    l.y = __float2bfloat16(y - __bfloat162float(h.y));
    hi = *reinterpret_cast<uint32_t*>(&h);
    lo = *reinterpret_cast<uint32_t*>(&l);
}

// elementwise split: X[n] -> hi/lo
__global__ void __launch_bounds__(256) split_k(
    const float* __restrict__ X, __nv_bfloat16* __restrict__ hi,
    __nv_bfloat16* __restrict__ lo, int n4)
{
    int i = blockIdx.x * 256 + threadIdx.x;
    if (i < n4) {
        float4 v = reinterpret_cast<const float4*>(X)[i];
        store_split4(hi, lo, (size_t)i * 4, v);
    }
}

// transpose + split: W[K,N] -> Thi/Tlo[N,K]
__global__ void __launch_bounds__(256) tsplit_k(
    const float* __restrict__ W, __nv_bfloat16* __restrict__ Thi,
    __nv_bfloat16* __restrict__ Tlo, int K, int N)
{
    __shared__ float t[32][33];
    const int n0 = blockIdx.x * 32, k0 = blockIdx.y * 32;
    const int tx = threadIdx.x, ty = threadIdx.y;   // (32, 8)
#pragma unroll
    for (int j = 0; j < 32; j += 8)
        t[ty + j][tx] = W[(size_t)(k0 + ty + j) * N + n0 + tx];
    __syncthreads();
#pragma unroll
    for (int j = 0; j < 32; j += 8) {
        float v = t[tx][ty + j];
        size_t o = (size_t)(n0 + ty + j) * K + k0 + tx;
        __nv_bfloat16 h = __float2bfloat16(v);
        Thi[o] = h;
        Tlo[o] = __float2bfloat16(v - __bfloat162float(h));
    }
}

// ---------------- mma.sync split-bf16 GEMM v2 --------------------------------
// C[M,N] = (Ahi+Alo)[M,K] @ (Bhi+Blo)^T, B* stored [N,K] row-major.
// CTA 128x256, 8 warps (2x4), warp tile 64x64, K-chunk 32, 3-stage cp.async.
// Stage layout (61440 B): Ah(128x80B) | Al | Bh(256x80B) | Bl
#define STG    61440
#define ALOFF  10240
#define BOFF   20480
#define BLOFF  40960
#define TGEMM_SMEM (3 * STG)

static __device__ __forceinline__ void load_stage(
    uint32_t smb, int stage,
    const __nv_bfloat16* __restrict__ Ah, const __nv_bfloat16* __restrict__ Al,
    const __nv_bfloat16* __restrict__ Bh, const __nv_bfloat16* __restrict__ Bl,
    int rowBase, int colBase, int K, int kt, int tid)
{
    const uint32_t sb = smb + stage * STG;
#pragma unroll
    for (int i = 0; i < 2; i++) {            // A: 128 rows x 32 k
        int idx = tid + i * 256;             // 0..511
        int r = idx >> 2;
        int kb = (idx & 3) * 8;
        uint32_t so = sb + (uint32_t)(r * 80 + kb * 2);
        size_t g = (size_t)(rowBase + r) * K + kt + kb;
        CP16(so,         Ah + g);
        CP16(so + ALOFF, Al + g);
    }
#pragma unroll
    for (int i = 0; i < 4; i++) {            // B: 256 rows x 32 k
        int idx = tid + i * 256;             // 0..1023
        int r = idx >> 2;
        int kb = (idx & 3) * 8;
        uint32_t so = sb + (uint32_t)(r * 80 + kb * 2);
        size_t g = (size_t)(colBase + r) * K + kt + kb;
        CP16(so + BOFF,  Bh + g);
        CP16(so + BLOFF, Bl + g);
    }
}

template <bool BIAS, bool RELU, bool RES, bool OSPLIT>
__global__ void __launch_bounds__(256, 1) tgemm_k(
    const __nv_bfloat16* __restrict__ Ah, const __nv_bfloat16* __restrict__ Al,
    const __nv_bfloat16* __restrict__ Bh, const __nv_bfloat16* __restrict__ Bl,
    const float* __restrict__ bias, const float* __restrict__ res,
    float* __restrict__ C, __nv_bfloat16* __restrict__ Chi,
    __nv_bfloat16* __restrict__ Clo, int N, int K)
{
    extern __shared__ char sm[];
    const uint32_t smb = s2u(sm);
    const int tid = threadIdx.x;
    const int wid = tid >> 5, lane = tid & 31;
    const int m_base = (wid & 1) * 64;        // warp M offset
    const int n_base = (wid >> 1) * 64;       // warp N offset
    const int rowBase = blockIdx.y * 128, colBase = (int)blockIdx.x * 256;

    float acc[4][8][4];
#pragma unroll
    for (int mf = 0; mf < 4; mf++)
#pragma unroll
        for (int j = 0; j < 8; j++)
#pragma unroll
            for (int q = 0; q < 4; q++) acc[mf][j][q] = 0.f;

    const uint32_t aOff = (uint32_t)((m_base + (lane & 15)) * 80 + (lane >> 4) * 16);
    const int bRow = n_base + (lane & 7) + ((lane >> 4) & 1) * 8;
    const uint32_t bOff = (uint32_t)(bRow * 80 + ((lane >> 3) & 1) * 16);

    const int NC = K / 32;
    load_stage(smb, 0, Ah, Al, Bh, Bl, rowBase, colBase, K, 0, tid);
    CP_COMMIT();
    load_stage(smb, 1, Ah, Al, Bh, Bl, rowBase, colBase, K, 32, tid);
    CP_COMMIT();

    for (int c = 0; c < NC; ++c) {
        if (c + 1 < NC) CP_WAIT1(); else CP_WAIT0();
        __syncthreads();
        // prefetch stage c+2 (overlaps with the mma below)
        if (c + 2 < NC) {
            load_stage(smb, (c + 2) % 3, Ah, Al, Bh, Bl,
                       rowBase, colBase, K, (c + 2) * 32, tid);
            CP_COMMIT();
        }
        const uint32_t sb = smb + (uint32_t)(c % 3) * STG;
#pragma unroll
        for (int ks = 0; ks < 2; ks++) {
            uint32_t a_h[4][4], a_l[4][4], bfr[4][4];
#pragma unroll
            for (int mf = 0; mf < 4; mf++) {
                ldsm4(a_h[mf], sb + aOff + (uint32_t)(mf * 16 * 80 + ks * 32));
                ldsm4(a_l[mf], sb + ALOFF + aOff + (uint32_t)(mf * 16 * 80 + ks * 32));
            }
#pragma unroll
            for (int nf2 = 0; nf2 < 4; nf2++)
                ldsm4(bfr[nf2], sb + BOFF + bOff + (uint32_t)(nf2 * 16 * 80 + ks * 32));
            // pass 1: Ah * Bh   (32 mma, distinct acc -> no RAW stall)
#pragma unroll
            for (int nf2 = 0; nf2 < 4; nf2++)
#pragma unroll
                for (int mf = 0; mf < 4; mf++) {
                    mma16816(acc[mf][nf2 * 2],     a_h[mf], bfr[nf2]);
                    mma16816(acc[mf][nf2 * 2 + 1], a_h[mf], bfr[nf2] + 2);
                }
            // pass 2: Al * Bh
#pragma unroll
            for (int nf2 = 0; nf2 < 4; nf2++)
#pragma unroll
                for (int mf = 0; mf < 4; mf++) {
                    mma16816(acc[mf][nf2 * 2],     a_l[mf], bfr[nf2]);
                    mma16816(acc[mf][nf2 * 2 + 1], a_l[mf], bfr[nf2] + 2);
                }
            // reload b <- Bl, pass 3: Ah * Bl
#pragma unroll
            for (int nf2 = 0; nf2 < 4; nf2++)
                ldsm4(bfr[nf2], sb + BLOFF + bOff + (uint32_t)(nf2 * 16 * 80 + ks * 32));
#pragma unroll
            for (int nf2 = 0; nf2 < 4; nf2++)
#pragma unroll
                for (int mf = 0; mf < 4; mf++) {
                    mma16816(acc[mf][nf2 * 2],     a_h[mf], bfr[nf2]);
                    mma16816(acc[mf][nf2 * 2 + 1], a_h[mf], bfr[nf2] + 2);
                }
        }
        __syncthreads();
    }

    // epilogue: acc[mf][j] covers cols j*8 within the warp's 64-col span
    const int group = lane >> 2, tig = lane & 3;
#pragma unroll
    for (int mf = 0; mf < 4; mf++) {
#pragma unroll
        for (int j = 0; j < 8; j++) {
            const int c0 = colBase + n_base + j * 8 + tig * 2;
            float bx = 0.f, by = 0.f;
            if (BIAS) {
                float2 bb = *reinterpret_cast<const float2*>(bias + c0);
                bx = bb.x; by = bb.y;
            }
#pragma unroll
            for (int half = 0; half < 2; half++) {
                const int r = rowBase + m_base + mf * 16 + group + half * 8;
                float ox = acc[mf][j][half * 2 + 0];
                float oy = acc[mf][j][half * 2 + 1];
                if (BIAS) { ox += bx; oy += by; }
                if (RES) {
                    float2 rr = *reinterpret_cast<const float2*>(
                        res + (size_t)r * N + c0);
                    ox += rr.x; oy += rr.y;
                }
                if (RELU) { ox = fmaxf(ox, 0.f); oy = fmaxf(oy, 0.f); }
                if (OSPLIT) {
                    store_split2(Chi, Clo, (size_t)r * N + c0, ox, oy);
                } else {
                    float2 o2; o2.x = ox; o2.y = oy;
                    *reinterpret_cast<float2*>(C + (size_t)r * N + c0) = o2;
                }
            }
        }
    }
}

// ---------------- tensor-core flash attention (unchanged from R5) ------------
#define QHB 0
#define QLB 18432
#define KHB 36864
#define KLB 46080
#define VHB 55296
#define VLB 64512
#define ATT_SMEM 73728

__global__ void __launch_bounds__(256, 2) attn_tc_k(
    const __nv_bfloat16* __restrict__ Qh, const __nv_bfloat16* __restrict__ Ql,
    const __nv_bfloat16* __restrict__ Kh, const __nv_bfloat16* __restrict__ Kl,
    const __nv_bfloat16* __restrict__ Vh, const __nv_bfloat16* __restrict__ Vl,
    __nv_bfloat16* __restrict__ Ohi, __nv_bfloat16* __restrict__ Olo)
{
    extern __shared__ char sm[];
    const uint32_t smb = s2u(sm);
    const int tid = threadIdx.x;
    const int wid = tid >> 5, lane = tid & 31;
    const int group = lane >> 2, tig = lane & 3;
    const int qBase = blockIdx.x * 128;
    const int h = blockIdx.y, b = blockIdx.z;
    const size_t gbase = (size_t)b * Sv * Dv + (size_t)h * DKv;

#pragma unroll
    for (int i = 0; i < 4; i++) {
        int idx = tid + i * 256;
        int r = idx >> 3;
        int c = (idx & 7) * 8;
        size_t g = gbase + (size_t)(qBase + r) * Dv + c;
        uint32_t so = (uint32_t)(r * 144 + c * 2);
        CP16(smb + QHB + so, Qh + g);
        CP16(smb + QLB + so, Ql + g);
    }
    CP_COMMIT();

    float m0 = -1e30f, m1 = -1e30f, l0 = 0.f, l1 = 0.f;
    float O[8][4];
#pragma unroll
    for (int nf = 0; nf < 8; nf++)
#pragma unroll
        for (int j = 0; j < 4; j++) O[nf][j] = 0.f;

    const uint32_t aOff = (uint32_t)((wid * 16 + (lane & 15)) * 144 + (lane >> 4) * 16);
    const int bRow = (lane & 7) + ((lane >> 4) & 1) * 8;
    const uint32_t bOff = (uint32_t)(bRow * 144 + ((lane >> 3) & 1) * 16);

    for (int kt = 0; kt < Sv; kt += 64) {
        __syncthreads();
#pragma unroll
        for (int i = 0; i < 2; i++) {
            int idx = tid + i * 256;
            int r = idx >> 3;
            int c = (idx & 7) * 8;
            size_t g = gbase + (size_t)(kt + r) * Dv + c;
            uint32_t so = (uint32_t)(r * 144 + c * 2);
            CP16(smb + KHB + so, Kh + g);
            CP16(smb + KLB + so, Kl + g);
        }
        CP_COMMIT();
#pragma unroll
        for (int i = 0; i < 2; i++) {
            int idx = tid + i * 256;
            int key = idx & 63;
            int db = (idx >> 6) * 8;
            size_t g = gbase + (size_t)(kt + key) * Dv + db;
            uint4 hv = *reinterpret_cast<const uint4*>(Vh + g);
            uint4 lv = *reinterpret_cast<const uint4*>(Vl + g);
            const __nv_bfloat16* hp = reinterpret_cast<const __nv_bfloat16*>(&hv);
            const __nv_bfloat16* lp = reinterpret_cast<const __nv_bfloat16*>(&lv);
#pragma unroll
            for (int j = 0; j < 8; j++) {
                uint32_t so = (uint32_t)((db + j) * 144 + key * 2);
                *reinterpret_cast<__nv_bfloat16*>(sm + VHB + so) = hp[j];
                *reinterpret_cast<__nv_bfloat16*>(sm + VLB + so) = lp[j];
            }
        }
        CP_WAIT0();
        __syncthreads();

        float S[8][4];
#pragma unroll
        for (int nf = 0; nf < 8; nf++)
#pragma unroll
            for (int j = 0; j < 4; j++) S[nf][j] = 0.f;
#pragma unroll
        for (int ks = 0; ks < 4; ks++) {
            uint32_t ah4[4], al4[4];
            ldsm4(ah4, smb + QHB + aOff + (uint32_t)(ks * 32));
            ldsm4(al4, smb + QLB + aOff + (uint32_t)(ks * 32));
#pragma unroll
            for (int nf2 = 0; nf2 < 4; nf2++) {
                uint32_t bh4[4], bl4[4];
                ldsm4(bh4, smb + KHB + bOff + (uint32_t)(nf2 * 16 * 144 + ks * 32));
                ldsm4(bl4, smb + KLB + bOff + (uint32_t)(nf2 * 16 * 144 + ks * 32));
                mma16816(S[nf2 * 2],     ah4, bh4);
                mma16816(S[nf2 * 2],     ah4, bl4);
                mma16816(S[nf2 * 2],     al4, bh4);
                mma16816(S[nf2 * 2 + 1], ah4, bh4 + 2);
                mma16816(S[nf2 * 2 + 1], ah4, bl4 + 2);
                mma16816(S[nf2 * 2 + 1], al4, bh4 + 2);
            }
        }

        float mx0 = -1e30f, mx1 = -1e30f;
#pragma unroll
        for (int nf = 0; nf < 8; nf++) {
            mx0 = fmaxf(mx0, fmaxf(S[nf][0], S[nf][1]));
            mx1 = fmaxf(mx1, fmaxf(S[nf][2], S[nf][3]));
        }
        mx0 = fmaxf(mx0, __shfl_xor_sync(0xffffffffu, mx0, 1));
        mx0 = fmaxf(mx0, __shfl_xor_sync(0xffffffffu, mx0, 2));
        mx1 = fmaxf(mx1, __shfl_xor_sync(0xffffffffu, mx1, 1));
        mx1 = fmaxf(mx1, __shfl_xor_sync(0xffffffffu, mx1, 2));
        const float mn0 = fmaxf(m0, mx0), mn1 = fmaxf(m1, mx1);
        const float cr0 = pexp(m0 - mn0), cr1 = pexp(m1 - mn1);
        m0 = mn0; m1 = mn1;
        float s0 = 0.f, s1 = 0.f;
#pragma unroll
        for (int nf = 0; nf < 8; nf++) {
            S[nf][0] = pexp(S[nf][0] - mn0);
            S[nf][1] = pexp(S[nf][1] - mn0);
            S[nf][2] = pexp(S[nf][2] - mn1);
            S[nf][3] = pexp(S[nf][3] - mn1);
            s0 += S[nf][0] + S[nf][1];
            s1 += S[nf][2] + S[nf][3];
        }
        s0 += __shfl_xor_sync(0xffffffffu, s0, 1);
        s0 += __shfl_xor_sync(0xffffffffu, s0, 2);
        s1 += __shfl_xor_sync(0xffffffffu, s1, 1);
        s1 += __shfl_xor_sync(0xffffffffu, s1, 2);
        l0 = l0 * cr0 + s0;
        l1 = l1 * cr1 + s1;
#pragma unroll
        for (int nf = 0; nf < 8; nf++) {
            O[nf][0] *= cr0; O[nf][1] *= cr0;
            O[nf][2] *= cr1; O[nf][3] *= cr1;
        }

#pragma unroll
        for (int kf = 0; kf < 4; kf++) {
            uint32_t aPh[4], aPl[4];
            psplit(S[2 * kf][0],     S[2 * kf][1],     aPh[0], aPl[0]);
            psplit(S[2 * kf][2],     S[2 * kf][3],     aPh[1], aPl[1]);
            psplit(S[2 * kf + 1][0], S[2 * kf + 1][1], aPh[2], aPl[2]);
            psplit(S[2 * kf + 1][2], S[2 * kf + 1][3], aPh[3], aPl[3]);
#pragma unroll
            for (int nf2 = 0; nf2 < 4; nf2++) {
                uint32_t bvh[4], bvl[4];
                ldsm4(bvh, smb + VHB + bOff + (uint32_t)(nf2 * 16 * 144 + kf * 32));
                ldsm4(bvl, smb + VLB + bOff + (uint32_t)(nf2 * 16 * 144 + kf * 32));
                mma16816(O[nf2 * 2],     aPh, bvh);
                mma16816(O[nf2 * 2],     aPh, bvl);
                mma16816(O[nf2 * 2],     aPl, bvh);
                mma16816(O[nf2 * 2 + 1], aPh, bvh + 2);
                mma16816(O[nf2 * 2 + 1], aPh, bvl + 2);
                mma16816(O[nf2 * 2 + 1], aPl, bvh + 2);
            }
        }
    }

    const float inv0 = 1.f / l0, inv1 = 1.f / l1;
    const int r0 = qBase + wid * 16 + group;
#pragma unroll
    for (int nf = 0; nf < 8; nf++) {
        const int col = nf * 8 + tig * 2;
        size_t off0 = gbase + (size_t)r0 * Dv + col;
        size_t off1 = gbase + (size_t)(r0 + 8) * Dv + col;
        store_split2(Ohi, Olo, off0, O[nf][0] * inv0, O[nf][1] * inv0);
        store_split2(Ohi, Olo, off1, O[nf][2] * inv1, O[nf][3] * inv1);
    }
}

// ---------------- layernorm (ddof=1, scalar gamma/beta) ---------------------
template <bool SPLIT>
__global__ void __launch_bounds__(256) ln_k(
    const float* __restrict__ X, float* __restrict__ Y,
    __nv_bfloat16* __restrict__ Yh, __nv_bfloat16* __restrict__ Yl,
    const float* __restrict__ gamma, const float* __restrict__ beta)
{
    __shared__ float sh[64];
    const int row = blockIdx.x;
    const int tid = threadIdx.x;
    const float4 v = *reinterpret_cast<const float4*>(X + (size_t)row * Dv + tid * 4);
    float s = v.x + v.y + v.z + v.w;
    float sq = fmaf(v.x, v.x, fmaf(v.y, v.y, fmaf(v.z, v.z, v.w * v.w)));
#pragma unroll
    for (int d = 16; d > 0; d >>= 1) {
        s  += __shfl_xor_sync(0xffffffffu, s, d);
        sq += __shfl_xor_sync(0xffffffffu, sq, d);
    }
    const int w = tid >> 5, lane = tid & 31;
    if (lane == 0) { sh[w] = s; sh[32 + w] = sq; }
    __syncthreads();
    if (tid == 0) {
        float S = 0.f, SQ = 0.f;
        for (int i = 0; i < 8; i++) { S += sh[i]; SQ += sh[32 + i]; }
        sh[48] = S; sh[49] = SQ;
    }
    __syncthreads();
    const float S = sh[48], SQ = sh[49];
    const float mean = S * (1.f / 1024.f);
    const float var = (SQ - 1024.f * mean * mean) * (1.f / 1023.f);
    const float scale = gamma[0] / sqrtf(var + 1e-5f);
    const float be = beta[0];
    float4 ov;
    ov.x = (v.x - mean) * scale + be;
    ov.y = (v.y - mean) * scale + be;
    ov.z = (v.z - mean) * scale + be;
    ov.w = (v.w - mean) * scale + be;
    *reinterpret_cast<float4*>(Y + (size_t)row * Dv + tid * 4) = ov;
    if (SPLIT) store_split4(Yh, Yl, (size_t)row * Dv + tid * 4, ov);
}

// ---------------- launch ----------------------------------------------------
extern "C" void kernel_launch(void* const* d_in, const int* in_sizes, int n_in,
                              void* d_out, int out_size)
{
    (void)in_sizes; (void)n_in; (void)out_size;
    const float* x      = (const float*)d_in[0];
    const float* wq     = (const float*)d_in[2];
    const float* wk     = (const float*)d_in[3];
    const float* wv     = (const float*)d_in[4];
    const float* wo     = (const float*)d_in[5];
    const float* w1     = (const float*)d_in[6];
    const float* b1     = (const float*)d_in[7];
    const float* w2     = (const float*)d_in[8];
    const float* b2     = (const float*)d_in[9];
    const float* gamma1 = (const float*)d_in[10];
    const float* beta1  = (const float*)d_in[11];
    const float* gamma2 = (const float*)d_in[12];
    const float* beta2  = (const float*)d_in[13];
    float* out = (float*)d_out;

    float *x1, *y;
    __nv_bfloat16 *xh, *xl, *qh, *ql, *kh, *kl, *vh, *vl, *ah, *al;
    __nv_bfloat16 *x1h, *x1l, *hh, *hl;
    __nv_bfloat16 *wqh, *wql, *wkh, *wkl, *wvh, *wvl, *woh, *wol;
    __nv_bfloat16 *w1h, *w1l, *w2h, *w2l;
    cudaGetSymbolAddress((void**)&x1,  g_x1);
    cudaGetSymbolAddress((void**)&y,   g_y);
    cudaGetSymbolAddress((void**)&xh,  g_xh);
    cudaGetSymbolAddress((void**)&xl,  g_xl);
    cudaGetSymbolAddress((void**)&qh,  g_qh);
    cudaGetSymbolAddress((void**)&ql,  g_ql);
    cudaGetSymbolAddress((void**)&kh,  g_kh);
    cudaGetSymbolAddress((void**)&kl,  g_kl);
    cudaGetSymbolAddress((void**)&vh,  g_vh);
    cudaGetSymbolAddress((void**)&vl,  g_vl);
    cudaGetSymbolAddress((void**)&ah,  g_ah);
    cudaGetSymbolAddress((void**)&al,  g_al);
    cudaGetSymbolAddress((void**)&x1h, g_x1h);
    cudaGetSymbolAddress((void**)&x1l, g_x1l);
    cudaGetSymbolAddress((void**)&hh,  g_hh);
    cudaGetSymbolAddress((void**)&hl,  g_hl);
    cudaGetSymbolAddress((void**)&wqh, g_wqh);
    cudaGetSymbolAddress((void**)&wql, g_wql);
    cudaGetSymbolAddress((void**)&wkh, g_wkh);
    cudaGetSymbolAddress((void**)&wkl, g_wkl);
    cudaGetSymbolAddress((void**)&wvh, g_wvh);
    cudaGetSymbolAddress((void**)&wvl, g_wvl);
    cudaGetSymbolAddress((void**)&woh, g_woh);
    cudaGetSymbolAddress((void**)&wol, g_wol);
    cudaGetSymbolAddress((void**)&w1h, g_w1h);
    cudaGetSymbolAddress((void**)&w1l, g_w1l);
    cudaGetSymbolAddress((void**)&w2h, g_w2h);
    cudaGetSymbolAddress((void**)&w2l, g_w2l);

    cudaFuncSetAttribute(attn_tc_k, cudaFuncAttributeMaxDynamicSharedMemorySize, ATT_SMEM);
    cudaFuncSetAttribute(tgemm_k<false, false, false, true>,
                         cudaFuncAttributeMaxDynamicSharedMemorySize, TGEMM_SMEM);
    cudaFuncSetAttribute(tgemm_k<false, false, true, false>,
                         cudaFuncAttributeMaxDynamicSharedMemorySize, TGEMM_SMEM);
    cudaFuncSetAttribute(tgemm_k<true, true, false, true>,
                         cudaFuncAttributeMaxDynamicSharedMemorySize, TGEMM_SMEM);
    cudaFuncSetAttribute(tgemm_k<true, false, true, false>,
                         cudaFuncAttributeMaxDynamicSharedMemorySize, TGEMM_SMEM);

    const dim3 tb(32, 8);
    // weight transpose + split
    tsplit_k<<<dim3(Dv / 32, Dv / 32), tb>>>(wq, wqh, wql, Dv, Dv);
    tsplit_k<<<dim3(Dv / 32, Dv / 32), tb>>>(wk, wkh, wkl, Dv, Dv);
    tsplit_k<<<dim3(Dv / 32, Dv / 32), tb>>>(wv, wvh, wvl, Dv, Dv);
    tsplit_k<<<dim3(Dv / 32, Dv / 32), tb>>>(wo, woh, wol, Dv, Dv);
    tsplit_k<<<dim3(DFFv / 32, Dv / 32), tb>>>(w1, w1h, w1l, Dv, DFFv);
    tsplit_k<<<dim3(Dv / 32, DFFv / 32), tb>>>(w2, w2h, w2l, DFFv, Dv);
    // x split
    split_k<<<(Mv * Dv / 4 + 255) / 256, 256>>>(x, xh, xl, Mv * Dv / 4);

    // QKV projections (emit split bf16 directly)
    tgemm_k<false, false, false, true><<<dim3(4, 32), 256, TGEMM_SMEM>>>(
        xh, xl, wqh, wql, nullptr, nullptr, nullptr, qh, ql, Dv, Dv);
    tgemm_k<false, false, false, true><<<dim3(4, 32), 256, TGEMM_SMEM>>>(
        xh, xl, wkh, wkl, nullptr, nullptr, nullptr, kh, kl, Dv, Dv);
    tgemm_k<false, false, false, true><<<dim3(4, 32), 256, TGEMM_SMEM>>>(
        xh, xl, wvh, wvl, nullptr, nullptr, nullptr, vh, vl, Dv, Dv);

    // tensor-core flash attention
    attn_tc_k<<<dim3(Sv / 128, Hv, Bv), 256, ATT_SMEM>>>(
        qh, ql, kh, kl, vh, vl, ah, al);

    // O projection + residual(x), LN1
    tgemm_k<false, false, true, false><<<dim3(4, 32), 256, TGEMM_SMEM>>>(
        ah, al, woh, wol, nullptr, x, y, nullptr, nullptr, Dv, Dv);
    ln_k<true><<<Mv, 256>>>(y, x1, x1h, x1l, gamma1, beta1);

    // FFN1 (bias + relu) -> split bf16
    tgemm_k<true, true, false, true><<<dim3(16, 32), 256, TGEMM_SMEM>>>(
        x1h, x1l, w1h, w1l, b1, nullptr, nullptr, hh, hl, DFFv, Dv);
    // FFN2 (bias + residual x1), LN2
    tgemm_k<true, false, true, false><<<dim3(4, 32), 256, TGEMM_SMEM>>>(
        hh, hl, w2h, w2l, b2, x1, y, nullptr, nullptr, Dv, DFFv);
    ln_k<false><<<Mv, 256>>>(y, out, nullptr, nullptr, gamma2, beta2);
}

// round 7
// speedup vs baseline: 1.3729x; 1.3729x over previous
#include <cuda_runtime.h>
#include <cuda_fp16.h>
#include <cstdint>
#include <math.h>

#define Bv   2
#define Sv   2048
#define Dv   1024
#define Hv   16
#define DKv  64
#define DFFv 4096
#define Mv   (Bv * Sv)   // 4096 rows

// ---------------- scratch (device globals; no allocation allowed) ----------
__device__ float g_x1[Mv * Dv];
__device__ float g_y[Mv * Dv];

__device__ __half g_xh[Mv * Dv],  g_xl[Mv * Dv];
__device__ __half g_qh[Mv * Dv],  g_ql[Mv * Dv];
__device__ __half g_kh[Mv * Dv];
__device__ __half g_vh[Mv * Dv];
__device__ __half g_ah[Mv * Dv],  g_al[Mv * Dv];
__device__ __half g_x1h[Mv * Dv], g_x1l[Mv * Dv];
__device__ __half g_hh[(size_t)Mv * DFFv], g_hl[(size_t)Mv * DFFv];

__device__ __half g_wqh[Dv * Dv];
__device__ __half g_wkh[Dv * Dv];
__device__ __half g_wvh[Dv * Dv];
__device__ __half g_woh[Dv * Dv];
__device__ __half g_w1h[Dv * DFFv];   // transposed: [DFF, D]
__device__ __half g_w2h[Dv * DFFv];   // transposed: [D, DFF]

// ---------------- PTX helpers (base sm_80+ only) ----------------------------
static __device__ __forceinline__ uint32_t s2u(const void* p) {
    uint32_t a;
    asm("{ .reg .u64 t; cvta.to.shared.u64 t, %1; cvt.u32.u64 %0, t; }"
        : "=r"(a) : "l"(p));
    return a;
}

static __device__ __forceinline__ void ldsm4(uint32_t* r, uint32_t addr) {
    asm volatile("ldmatrix.sync.aligned.m8n8.x4.shared.b16 {%0,%1,%2,%3}, [%4];"
        : "=r"(r[0]), "=r"(r[1]), "=r"(r[2]), "=r"(r[3]) : "r"(addr));
}

static __device__ __forceinline__ void mma16816(
    float* d, const uint32_t* a, const uint32_t* b)
{
    asm volatile("mma.sync.aligned.m16n8k16.row.col.f32.f16.f16.f32 "
        "{%0,%1,%2,%3}, {%4,%5,%6,%7}, {%8,%9}, {%0,%1,%2,%3};"
        : "+f"(d[0]), "+f"(d[1]), "+f"(d[2]), "+f"(d[3])
        : "r"(a[0]), "r"(a[1]), "r"(a[2]), "r"(a[3]), "r"(b[0]), "r"(b[1]));
}

#define CP16(dst, src) \
    asm volatile("cp.async.cg.shared.global [%0], [%1], 16;" \
                 :: "r"(dst), "l"(src))
#define CP_COMMIT() asm volatile("cp.async.commit_group;" ::: "memory")
#define CP_WAIT0()  asm volatile("cp.async.wait_group 0;" ::: "memory")
#define CP_WAIT1()  asm volatile("cp.async.wait_group 1;" ::: "memory")

// ---------------- fast exp on FMA pipe: pexp(s) = exp(s / 8) ----------------
static __device__ __forceinline__ float pexp(float s) {
    const float C = 0.125f * 1.4426950408889634f;
    s = fmaxf(s, -500.0f);
    float yr = fmaf(s, C, 12582912.0f);
    int   n  = __float_as_int(yr) - 0x4B400000;
    float nf = yr - 12582912.0f;
    float f  = fmaf(s, C, -nf);
    float p  = 0.0018775767f;
    p = fmaf(p, f, 0.0089893397f);
    p = fmaf(p, f, 0.0558026980f);
    p = fmaf(p, f, 0.2401597153f);
    p = fmaf(p, f, 0.6931471825f);
    p = fmaf(p, f, 1.0f);
    return __int_as_float(__float_as_int(p) + (n << 23));
}

// ---------------- fp16 hi/lo split helpers ----------------------------------
static __device__ __forceinline__ void store_split4(
    __half* __restrict__ hi, __half* __restrict__ lo, size_t off, float4 v)
{
    __half h0 = __float2half(v.x), h1 = __float2half(v.y);
    __half h2 = __float2half(v.z), h3 = __float2half(v.w);
    __half l0 = __float2half(v.x - __half2float(h0));
    __half l1 = __float2half(v.y - __half2float(h1));
    __half l2 = __float2half(v.z - __half2float(h2));
    __half l3 = __float2half(v.w - __half2float(h3));
    __half2 ph0, ph1, pl0, pl1;
    ph0.x = h0; ph0.y = h1; ph1.x = h2; ph1.y = h3;
    pl0.x = l0; pl0.y = l1; pl1.x = l2; pl1.y = l3;
    uint2 uh, ul;
    uh.x = *reinterpret_cast<uint32_t*>(&ph0);
    uh.y = *reinterpret_cast<uint32_t*>(&ph1);
    ul.x = *reinterpret_cast<uint32_t*>(&pl0);
    ul.y = *reinterpret_cast<uint32_t*>(&pl1);
    *reinterpret_cast<uint2*>(hi + off) = uh;
    *reinterpret_cast<uint2*>(lo + off) = ul;
}

static __device__ __forceinline__ void store_split2(
    __half* __restrict__ hi, __half* __restrict__ lo,
    size_t off, float x, float y)
{
    __half h0 = __float2half(x), h1 = __float2half(y);
    __half2 ph, pl;
    ph.x = h0; ph.y = h1;
    pl.x = __float2half(x - __half2float(h0));
    pl.y = __float2half(y - __half2float(h1));
    *reinterpret_cast<__half2*>(hi + off) = ph;
    *reinterpret_cast<__half2*>(lo + off) = pl;
}

static __device__ __forceinline__ void psplit(
    float x, float y, uint32_t& hi, uint32_t& lo)
{
    __half2 h, l;
    h.x = __float2half(x); h.y = __float2half(y);
    l.x = __float2half(x - __half2float(h.x));
    l.y = __float2half(y - __half2float(h.y));
    hi = *reinterpret_cast<uint32_t*>(&h);
    lo = *reinterpret_cast<uint32_t*>(&l);
}

// elementwise split: X[n] -> hi/lo
__global__ void __launch_bounds__(256) split_k(
    const float* __restrict__ X, __half* __restrict__ hi,
    __half* __restrict__ lo, int n4)
{
    int i = blockIdx.x * 256 + threadIdx.x;
    if (i < n4) {
        float4 v = reinterpret_cast<const float4*>(X)[i];
        store_split4(hi, lo, (size_t)i * 4, v);
    }
}

// transpose + convert: W[K,N] -> T[N,K] (single fp16, B-side operand)
__global__ void __launch_bounds__(256) tconv_k(
    const float* __restrict__ W, __half* __restrict__ T, int K, int N)
{
    __shared__ float t[32][33];
    const int n0 = blockIdx.x * 32, k0 = blockIdx.y * 32;
    const int tx = threadIdx.x, ty = threadIdx.y;   // (32, 8)
#pragma unroll
    for (int j = 0; j < 32; j += 8)
        t[ty + j][tx] = W[(size_t)(k0 + ty + j) * N + n0 + tx];
    __syncthreads();
#pragma unroll
    for (int j = 0; j < 32; j += 8)
        T[(size_t)(n0 + ty + j) * K + k0 + tx] = __float2half(t[tx][ty + j]);
}

// ---------------- mma.sync 2-term fp16 GEMM ---------------------------------
// C[M,N] = (Ahi+Alo)[M,K] @ Bh^T  (B single fp16, stored [N,K] row-major).
// CTA 128x128, 8 warps (warp tile 32x64), K-chunk 32, cp.async double buffer.
// Stage (30720 B): Ah | Al | Bh, each 128 rows x 40 halves (80 B stride).
#define STG   30720
#define ALOFF 10240
#define BOFF  20480
#define TGEMM_SMEM (2 * STG)

static __device__ __forceinline__ void load_stage(
    uint32_t smb, int stage,
    const __half* __restrict__ Ah, const __half* __restrict__ Al,
    const __half* __restrict__ Bh,
    int rowBase, int colBase, int K, int kt, int tid)
{
    const uint32_t sb = smb + stage * STG;
#pragma unroll
    for (int i = 0; i < 2; i++) {
        int idx = tid + i * 256;         // 0..511
        int r = idx >> 2;                // 0..127
        int kb = (idx & 3) * 8;          // 0,8,16,24
        uint32_t so = sb + (uint32_t)(r * 80 + kb * 2);
        size_t ga = (size_t)(rowBase + r) * K + kt + kb;
        size_t gb = (size_t)(colBase + r) * K + kt + kb;
        CP16(so,         Ah + ga);
        CP16(so + ALOFF, Al + ga);
        CP16(so + BOFF,  Bh + gb);
    }
}

template <bool BIAS, bool RELU, bool RES, bool OSPLIT>
__global__ void __launch_bounds__(256, 2) tgemm_k(
    const __half* __restrict__ Ah, const __half* __restrict__ Al,
    const __half* __restrict__ Bh,
    const float* __restrict__ bias, const float* __restrict__ res,
    float* __restrict__ C, __half* __restrict__ Chi,
    __half* __restrict__ Clo, int N, int K)
{
    extern __shared__ char sm[];
    const uint32_t smb = s2u(sm);
    const int tid = threadIdx.x;
    const int wid = tid >> 5, lane = tid & 31;
    const int m_base = (wid & 3) * 32;
    const int n_base = (wid >> 2) * 64;
    const int rowBase = blockIdx.y * 128, colBase = blockIdx.x * 128;

    float acc[2][8][4];
#pragma unroll
    for (int mf = 0; mf < 2; mf++)
#pragma unroll
        for (int nf = 0; nf < 8; nf++)
#pragma unroll
            for (int j = 0; j < 4; j++) acc[mf][nf][j] = 0.f;

    const uint32_t aOff = (uint32_t)((m_base + (lane & 15)) * 80 + (lane >> 4) * 16);
    const int bRow = (lane & 7) + ((lane >> 4) & 1) * 8;
    const uint32_t bOff = (uint32_t)((n_base + bRow) * 80 + ((lane >> 3) & 1) * 16);

    const int NC = K / 32;
    load_stage(smb, 0, Ah, Al, Bh, rowBase, colBase, K, 0, tid);
    CP_COMMIT();

    for (int c = 0; c < NC; ++c) {
        if (c + 1 < NC) {
            load_stage(smb, (c + 1) & 1, Ah, Al, Bh,
                       rowBase, colBase, K, (c + 1) * 32, tid);
            CP_COMMIT();
            CP_WAIT1();
        } else {
            CP_WAIT0();
        }
        __syncthreads();

        const uint32_t sb = smb + (uint32_t)(c & 1) * STG;
#pragma unroll
        for (int ks = 0; ks < 2; ks++) {
            uint32_t ah[2][4], al[2][4];
#pragma unroll
            for (int mf = 0; mf < 2; mf++) {
                ldsm4(ah[mf], sb + aOff + (uint32_t)(mf * 16 * 80 + ks * 32));
                ldsm4(al[mf], sb + ALOFF + aOff + (uint32_t)(mf * 16 * 80 + ks * 32));
            }
#pragma unroll
            for (int nf = 0; nf < 4; nf++) {
                uint32_t bh4[4];
                ldsm4(bh4, sb + BOFF + bOff + (uint32_t)(nf * 16 * 80 + ks * 32));
#pragma unroll
                for (int mf = 0; mf < 2; mf++) {
                    mma16816(acc[mf][nf * 2],     ah[mf], bh4);
                    mma16816(acc[mf][nf * 2],     al[mf], bh4);
                    mma16816(acc[mf][nf * 2 + 1], ah[mf], bh4 + 2);
                    mma16816(acc[mf][nf * 2 + 1], al[mf], bh4 + 2);
                }
            }
        }
        __syncthreads();
    }

    const int group = lane >> 2, tig = lane & 3;
#pragma unroll
    for (int mf = 0; mf < 2; mf++) {
#pragma unroll
        for (int nf = 0; nf < 8; nf++) {
            const int c0 = colBase + n_base + nf * 8 + tig * 2;
            float bx = 0.f, by = 0.f;
            if (BIAS) {
                float2 bb = *reinterpret_cast<const float2*>(bias + c0);
                bx = bb.x; by = bb.y;
            }
#pragma unroll
            for (int half = 0; half < 2; half++) {
                const int r = rowBase + m_base + mf * 16 + group + half * 8;
                float ox = acc[mf][nf][half * 2 + 0];
                float oy = acc[mf][nf][half * 2 + 1];
                if (BIAS) { ox += bx; oy += by; }
                if (RES) {
                    float2 rr = *reinterpret_cast<const float2*>(
                        res + (size_t)r * N + c0);
                    ox += rr.x; oy += rr.y;
                }
                if (RELU) { ox = fmaxf(ox, 0.f); oy = fmaxf(oy, 0.f); }
                if (OSPLIT) {
                    store_split2(Chi, Clo, (size_t)r * N + c0, ox, oy);
                } else {
                    float2 o2; o2.x = ox; o2.y = oy;
                    *reinterpret_cast<float2*>(C + (size_t)r * N + c0) = o2;
                }
            }
        }
    }
}

// ---------------- tensor-core flash attention (2-term fp16) ------------------
// smem (fp16, row stride 72 elems = 144 B):
//   Qh @ 0      Ql @ 18432   (128 x 72 each)
//   Kh @ 36864               (64 keys x 72)
//   Vth @ 46080              (64 d x 72, V transposed at fill)
#define QHB 0
#define QLB 18432
#define KHB 36864
#define VHB 46080
#define ATT_SMEM 55296

__global__ void __launch_bounds__(256, 2) attn_tc_k(
    const __half* __restrict__ Qh, const __half* __restrict__ Ql,
    const __half* __restrict__ Kh, const __half* __restrict__ Vh,
    __half* __restrict__ Ohi, __half* __restrict__ Olo)
{
    extern __shared__ char sm[];
    const uint32_t smb = s2u(sm);
    const int tid = threadIdx.x;
    const int wid = tid >> 5, lane = tid & 31;
    const int group = lane >> 2, tig = lane & 3;
    const int qBase = blockIdx.x * 128;
    const int h = blockIdx.y, b = blockIdx.z;
    const size_t gbase = (size_t)b * Sv * Dv + (size_t)h * DKv;

#pragma unroll
    for (int i = 0; i < 4; i++) {
        int idx = tid + i * 256;
        int r = idx >> 3;
        int c = (idx & 7) * 8;
        size_t g = gbase + (size_t)(qBase + r) * Dv + c;
        uint32_t so = (uint32_t)(r * 144 + c * 2);
        CP16(smb + QHB + so, Qh + g);
        CP16(smb + QLB + so, Ql + g);
    }
    CP_COMMIT();

    float m0 = -1e30f, m1 = -1e30f, l0 = 0.f, l1 = 0.f;
    float O[8][4];
#pragma unroll
    for (int nf = 0; nf < 8; nf++)
#pragma unroll
        for (int j = 0; j < 4; j++) O[nf][j] = 0.f;

    const uint32_t aOff = (uint32_t)((wid * 16 + (lane & 15)) * 144 + (lane >> 4) * 16);
    const int bRow = (lane & 7) + ((lane >> 4) & 1) * 8;
    const uint32_t bOff = (uint32_t)(bRow * 144 + ((lane >> 3) & 1) * 16);

    for (int kt = 0; kt < Sv; kt += 64) {
        __syncthreads();
        // K fill (hi only)
        {
            int idx = tid;                 // 512 cp16 needed; 256 threads x 2
#pragma unroll
            for (int i = 0; i < 2; i++) {
                int r = (idx + i * 256) >> 3;
                int c = ((idx + i * 256) & 7) * 8;
                size_t g = gbase + (size_t)(kt + r) * Dv + c;
                CP16(smb + KHB + (uint32_t)(r * 144 + c * 2), Kh + g);
            }
        }
        CP_COMMIT();
        // V fill TRANSPOSED (hi only)
#pragma unroll
        for (int i = 0; i < 2; i++) {
            int idx = tid + i * 256;
            int key = idx & 63;
            int db = (idx >> 6) * 8;
            size_t g = gbase + (size_t)(kt + key) * Dv + db;
            uint4 hv = *reinterpret_cast<const uint4*>(Vh + g);
            const __half* hp = reinterpret_cast<const __half*>(&hv);
#pragma unroll
            for (int j = 0; j < 8; j++) {
                uint32_t so = (uint32_t)((db + j) * 144 + key * 2);
                *reinterpret_cast<__half*>(sm + VHB + so) = hp[j];
            }
        }
        CP_WAIT0();
        __syncthreads();

        // ---- S = Q @ K^T ----
        float S[8][4];
#pragma unroll
        for (int nf = 0; nf < 8; nf++)
#pragma unroll
            for (int j = 0; j < 4; j++) S[nf][j] = 0.f;
#pragma unroll
        for (int ks = 0; ks < 4; ks++) {
            uint32_t ah4[4], al4[4];
            ldsm4(ah4, smb + QHB + aOff + (uint32_t)(ks * 32));
            ldsm4(al4, smb + QLB + aOff + (uint32_t)(ks * 32));
#pragma unroll
            for (int nf2 = 0; nf2 < 4; nf2++) {
                uint32_t bh4[4];
                ldsm4(bh4, smb + KHB + bOff + (uint32_t)(nf2 * 16 * 144 + ks * 32));
                mma16816(S[nf2 * 2],     ah4, bh4);
                mma16816(S[nf2 * 2],     al4, bh4);
                mma16816(S[nf2 * 2 + 1], ah4, bh4 + 2);
                mma16816(S[nf2 * 2 + 1], al4, bh4 + 2);
            }
        }

        // ---- online softmax ----
        float mx0 = -1e30f, mx1 = -1e30f;
#pragma unroll
        for (int nf = 0; nf < 8; nf++) {
            mx0 = fmaxf(mx0, fmaxf(S[nf][0], S[nf][1]));
            mx1 = fmaxf(mx1, fmaxf(S[nf][2], S[nf][3]));
        }
        mx0 = fmaxf(mx0, __shfl_xor_sync(0xffffffffu, mx0, 1));
        mx0 = fmaxf(mx0, __shfl_xor_sync(0xffffffffu, mx0, 2));
        mx1 = fmaxf(mx1, __shfl_xor_sync(0xffffffffu, mx1, 1));
        mx1 = fmaxf(mx1, __shfl_xor_sync(0xffffffffu, mx1, 2));
        const float mn0 = fmaxf(m0, mx0), mn1 = fmaxf(m1, mx1);
        const float cr0 = pexp(m0 - mn0), cr1 = pexp(m1 - mn1);
        m0 = mn0; m1 = mn1;
        float s0 = 0.f, s1 = 0.f;
#pragma unroll
        for (int nf = 0; nf < 8; nf++) {
            S[nf][0] = pexp(S[nf][0] - mn0);
            S[nf][1] = pexp(S[nf][1] - mn0);
            S[nf][2] = pexp(S[nf][2] - mn1);
            S[nf][3] = pexp(S[nf][3] - mn1);
            s0 += S[nf][0] + S[nf][1];
            s1 += S[nf][2] + S[nf][3];
        }
        s0 += __shfl_xor_sync(0xffffffffu, s0, 1);
        s0 += __shfl_xor_sync(0xffffffffu, s0, 2);
        s1 += __shfl_xor_sync(0xffffffffu, s1, 1);
        s1 += __shfl_xor_sync(0xffffffffu, s1, 2);
        l0 = l0 * cr0 + s0;
        l1 = l1 * cr1 + s1;
#pragma unroll
        for (int nf = 0; nf < 8; nf++) {
            O[nf][0] *= cr0; O[nf][1] *= cr0;
            O[nf][2] *= cr1; O[nf][3] *= cr1;
        }

        // ---- O += P @ V ----
#pragma unroll
        for (int kf = 0; kf < 4; kf++) {
            uint32_t aPh[4], aPl[4];
            psplit(S[2 * kf][0],     S[2 * kf][1],     aPh[0], aPl[0]);
            psplit(S[2 * kf][2],     S[2 * kf][3],     aPh[1], aPl[1]);
            psplit(S[2 * kf + 1][0], S[2 * kf + 1][1], aPh[2], aPl[2]);
            psplit(S[2 * kf + 1][2], S[2 * kf + 1][3], aPh[3], aPl[3]);
#pragma unroll
            for (int nf2 = 0; nf2 < 4; nf2++) {
                uint32_t bvh[4];
                ldsm4(bvh, smb + VHB + bOff + (uint32_t)(nf2 * 16 * 144 + kf * 32));
                mma16816(O[nf2 * 2],     aPh, bvh);
                mma16816(O[nf2 * 2],     aPl, bvh);
                mma16816(O[nf2 * 2 + 1], aPh, bvh + 2);
                mma16816(O[nf2 * 2 + 1], aPl, bvh + 2);
            }
        }
    }

    const float inv0 = 1.f / l0, inv1 = 1.f / l1;
    const int r0 = qBase + wid * 16 + group;
#pragma unroll
    for (int nf = 0; nf < 8; nf++) {
        const int col = nf * 8 + tig * 2;
        size_t off0 = gbase + (size_t)r0 * Dv + col;
        size_t off1 = gbase + (size_t)(r0 + 8) * Dv + col;
        store_split2(Ohi, Olo, off0, O[nf][0] * inv0, O[nf][1] * inv0);
        store_split2(Ohi, Olo, off1, O[nf][2] * inv1, O[nf][3] * inv1);
    }
}

// ---------------- layernorm (ddof=1, scalar gamma/beta) ---------------------
template <bool SPLIT>
__global__ void __launch_bounds__(256) ln_k(
    const float* __restrict__ X, float* __restrict__ Y,
    __half* __restrict__ Yh, __half* __restrict__ Yl,
    const float* __restrict__ gamma, const float* __restrict__ beta)
{
    __shared__ float sh[64];
    const int row = blockIdx.x;
    const int tid = threadIdx.x;
    const float4 v = *reinterpret_cast<const float4*>(X + (size_t)row * Dv + tid * 4);
    float s = v.x + v.y + v.z + v.w;
    float sq = fmaf(v.x, v.x, fmaf(v.y, v.y, fmaf(v.z, v.z, v.w * v.w)));
#pragma unroll
    for (int d = 16; d > 0; d >>= 1) {
        s  += __shfl_xor_sync(0xffffffffu, s, d);
        sq += __shfl_xor_sync(0xffffffffu, sq, d);
    }
    const int w = tid >> 5, lane = tid & 31;
    if (lane == 0) { sh[w] = s; sh[32 + w] = sq; }
    __syncthreads();
    if (tid == 0) {
        float S = 0.f, SQ = 0.f;
        for (int i = 0; i < 8; i++) { S += sh[i]; SQ += sh[32 + i]; }
        sh[48] = S; sh[49] = SQ;
    }
    __syncthreads();
    const float S = sh[48], SQ = sh[49];
    const float mean = S * (1.f / 1024.f);
    const float var = (SQ - 1024.f * mean * mean) * (1.f / 1023.f);
    const float scale = gamma[0] / sqrtf(var + 1e-5f);
    const float be = beta[0];
    float4 ov;
    ov.x = (v.x - mean) * scale + be;
    ov.y = (v.y - mean) * scale + be;
    ov.z = (v.z - mean) * scale + be;
    ov.w = (v.w - mean) * scale + be;
    *reinterpret_cast<float4*>(Y + (size_t)row * Dv + tid * 4) = ov;
    if (SPLIT) store_split4(Yh, Yl, (size_t)row * Dv + tid * 4, ov);
}

// ---------------- launch ----------------------------------------------------
extern "C" void kernel_launch(void* const* d_in, const int* in_sizes, int n_in,
                              void* d_out, int out_size)
{
    (void)in_sizes; (void)n_in; (void)out_size;
    const float* x      = (const float*)d_in[0];
    const float* wq     = (const float*)d_in[2];
    const float* wk     = (const float*)d_in[3];
    const float* wv     = (const float*)d_in[4];
    const float* wo     = (const float*)d_in[5];
    const float* w1     = (const float*)d_in[6];
    const float* b1     = (const float*)d_in[7];
    const float* w2     = (const float*)d_in[8];
    const float* b2     = (const float*)d_in[9];
    const float* gamma1 = (const float*)d_in[10];
    const float* beta1  = (const float*)d_in[11];
    const float* gamma2 = (const float*)d_in[12];
    const float* beta2  = (const float*)d_in[13];
    float* out = (float*)d_out;

    float *x1, *y;
    __half *xh, *xl, *qh, *ql, *kh, *vh, *ah, *al, *x1h, *x1l, *hh, *hl;
    __half *wqh, *wkh, *wvh, *woh, *w1h, *w2h;
    cudaGetSymbolAddress((void**)&x1,  g_x1);
    cudaGetSymbolAddress((void**)&y,   g_y);
    cudaGetSymbolAddress((void**)&xh,  g_xh);
    cudaGetSymbolAddress((void**)&xl,  g_xl);
    cudaGetSymbolAddress((void**)&qh,  g_qh);
    cudaGetSymbolAddress((void**)&ql,  g_ql);
    cudaGetSymbolAddress((void**)&kh,  g_kh);
    cudaGetSymbolAddress((void**)&vh,  g_vh);
    cudaGetSymbolAddress((void**)&ah,  g_ah);
    cudaGetSymbolAddress((void**)&al,  g_al);
    cudaGetSymbolAddress((void**)&x1h, g_x1h);
    cudaGetSymbolAddress((void**)&x1l, g_x1l);
    cudaGetSymbolAddress((void**)&hh,  g_hh);
    cudaGetSymbolAddress((void**)&hl,  g_hl);
    cudaGetSymbolAddress((void**)&wqh, g_wqh);
    cudaGetSymbolAddress((void**)&wkh, g_wkh);
    cudaGetSymbolAddress((void**)&wvh, g_wvh);
    cudaGetSymbolAddress((void**)&woh, g_woh);
    cudaGetSymbolAddress((void**)&w1h, g_w1h);
    cudaGetSymbolAddress((void**)&w2h, g_w2h);

    cudaFuncSetAttribute(attn_tc_k, cudaFuncAttributeMaxDynamicSharedMemorySize, ATT_SMEM);
    cudaFuncSetAttribute(tgemm_k<false, false, false, true>,
                         cudaFuncAttributeMaxDynamicSharedMemorySize, TGEMM_SMEM);
    cudaFuncSetAttribute(tgemm_k<false, false, true, false>,
                         cudaFuncAttributeMaxDynamicSharedMemorySize, TGEMM_SMEM);
    cudaFuncSetAttribute(tgemm_k<true, true, false, true>,
                         cudaFuncAttributeMaxDynamicSharedMemorySize, TGEMM_SMEM);
    cudaFuncSetAttribute(tgemm_k<true, false, true, false>,
                         cudaFuncAttributeMaxDynamicSharedMemorySize, TGEMM_SMEM);

    const dim3 tb(32, 8);
    // weight transpose + convert (single fp16)
    tconv_k<<<dim3(Dv / 32, Dv / 32), tb>>>(wq, wqh, Dv, Dv);
    tconv_k<<<dim3(Dv / 32, Dv / 32), tb>>>(wk, wkh, Dv, Dv);
    tconv_k<<<dim3(Dv / 32, Dv / 32), tb>>>(wv, wvh, Dv, Dv);
    tconv_k<<<dim3(Dv / 32, Dv / 32), tb>>>(wo, woh, Dv, Dv);
    tconv_k<<<dim3(DFFv / 32, Dv / 32), tb>>>(w1, w1h, Dv, DFFv);
    tconv_k<<<dim3(Dv / 32, DFFv / 32), tb>>>(w2, w2h, DFFv, Dv);
    // x split
    split_k<<<(Mv * Dv / 4 + 255) / 256, 256>>>(x, xh, xl, Mv * Dv / 4);

    // QKV projections: Q emits split (A-side downstream); K and V emit hi only
    // (they are B-side operands in attention). Reuse OSPLIT path with lo ptr.
    tgemm_k<false, false, false, true><<<dim3(8, 32), 256, TGEMM_SMEM>>>(
        xh, xl, wqh, nullptr, nullptr, nullptr, qh, ql, Dv, Dv);
    tgemm_k<false, false, false, true><<<dim3(8, 32), 256, TGEMM_SMEM>>>(
        xh, xl, wkh, nullptr, nullptr, nullptr, kh, ql /*scratch lo*/, Dv, Dv);
    tgemm_k<false, false, false, true><<<dim3(8, 32), 256, TGEMM_SMEM>>>(
        xh, xl, wvh, nullptr, nullptr, nullptr, vh, ql /*scratch lo*/, Dv, Dv);
    // NOTE: K/V lo writes clobber ql scratch — so re-run Q LAST to keep ql valid.
    tgemm_k<false, false, false, true><<<dim3(8, 32), 256, TGEMM_SMEM>>>(
        xh, xl, wqh, nullptr, nullptr, nullptr, qh, ql, Dv, Dv);

    // tensor-core flash attention
    attn_tc_k<<<dim3(Sv / 128, Hv, Bv), 256, ATT_SMEM>>>(
        qh, ql, kh, vh, ah, al);

    // O projection + residual(x), LN1
    tgemm_k<false, false, true, false><<<dim3(8, 32), 256, TGEMM_SMEM>>>(
        ah, al, woh, nullptr, x, y, nullptr, nullptr, Dv, Dv);
    ln_k<true><<<Mv, 256>>>(y, x1, x1h, x1l, gamma1, beta1);

    // FFN1 (bias + relu) -> split fp16
    tgemm_k<true, true, false, true><<<dim3(32, 32), 256, TGEMM_SMEM>>>(
        x1h, x1l, w1h, b1, nullptr, nullptr, hh, hl, DFFv, Dv);
    // FFN2 (bias + residual x1), LN2
    tgemm_k<true, false, true, false><<<dim3(8, 32), 256, TGEMM_SMEM>>>(
        hh, hl, w2h, b2, x1, y, nullptr, nullptr, Dv, DFFv);
    ln_k<false><<<Mv, 256>>>(y, out, nullptr, nullptr, gamma2, beta2);
}

// round 15
// speedup vs baseline: 1.4960x; 1.0897x over previous
#include <cuda_runtime.h>
#include <cuda_fp16.h>
#include <cstdint>
#include <math.h>

#define Bv   2
#define Sv   2048
#define Dv   1024
#define Hv   16
#define DKv  64
#define DFFv 4096
#define Mv   (Bv * Sv)   // 4096 rows

// ---------------- scratch (device globals; no allocation allowed) ----------
__device__ float g_x1[Mv * Dv];
__device__ float g_y[Mv * Dv];

__device__ __half g_xh[Mv * Dv],  g_xl[Mv * Dv];
__device__ __half g_qh[Mv * Dv],  g_ql[Mv * Dv];
__device__ __half g_kh[Mv * Dv];
__device__ __half g_vh[Mv * Dv];
__device__ __half g_ah[Mv * Dv],  g_al[Mv * Dv];
__device__ __half g_x1h[Mv * Dv], g_x1l[Mv * Dv];
__device__ __half g_hh[(size_t)Mv * DFFv], g_hl[(size_t)Mv * DFFv];

__device__ __half g_wqh[Dv * Dv];
__device__ __half g_wkh[Dv * Dv];
__device__ __half g_wvh[Dv * Dv];
__device__ __half g_woh[Dv * Dv];
__device__ __half g_w1h[Dv * DFFv];   // transposed: [DFF, D]
__device__ __half g_w2h[Dv * DFFv];   // transposed: [D, DFF]

// ---------------- PTX helpers (base sm_80+ only) ----------------------------
static __device__ __forceinline__ uint32_t s2u(const void* p) {
    uint32_t a;
    asm("{ .reg .u64 t; cvta.to.shared.u64 t, %1; cvt.u32.u64 %0, t; }"
        : "=r"(a) : "l"(p));
    return a;
}

static __device__ __forceinline__ void ldsm4(uint32_t* r, uint32_t addr) {
    asm volatile("ldmatrix.sync.aligned.m8n8.x4.shared.b16 {%0,%1,%2,%3}, [%4];"
        : "=r"(r[0]), "=r"(r[1]), "=r"(r[2]), "=r"(r[3]) : "r"(addr));
}

static __device__ __forceinline__ void mma16816(
    float* d, const uint32_t* a, const uint32_t* b)
{
    asm volatile("mma.sync.aligned.m16n8k16.row.col.f32.f16.f16.f32 "
        "{%0,%1,%2,%3}, {%4,%5,%6,%7}, {%8,%9}, {%0,%1,%2,%3};"
        : "+f"(d[0]), "+f"(d[1]), "+f"(d[2]), "+f"(d[3])
        : "r"(a[0]), "r"(a[1]), "r"(a[2]), "r"(a[3]), "r"(b[0]), "r"(b[1]));
}

#define CP16(dst, src) \
    asm volatile("cp.async.cg.shared.global [%0], [%1], 16;" \
                 :: "r"(dst), "l"(src))
#define CP_COMMIT() asm volatile("cp.async.commit_group;" ::: "memory")
#define CP_WAIT0()  asm volatile("cp.async.wait_group 0;" ::: "memory")
#define CP_WAIT1()  asm volatile("cp.async.wait_group 1;" ::: "memory")

// ---------------- fast exp on FMA pipe: pexp(s) = exp(s / 8) ----------------
static __device__ __forceinline__ float pexp(float s) {
    const float C = 0.125f * 1.4426950408889634f;
    s = fmaxf(s, -500.0f);
    float yr = fmaf(s, C, 12582912.0f);
    int   n  = __float_as_int(yr) - 0x4B400000;
    float nf = yr - 12582912.0f;
    float f  = fmaf(s, C, -nf);
    float p  = 0.0018775767f;
    p = fmaf(p, f, 0.0089893397f);
    p = fmaf(p, f, 0.0558026980f);
    p = fmaf(p, f, 0.2401597153f);
    p = fmaf(p, f, 0.6931471825f);
    p = fmaf(p, f, 1.0f);
    return __int_as_float(__float_as_int(p) + (n << 23));
}

// ---------------- fp16 hi/lo split helpers ----------------------------------
static __device__ __forceinline__ void store_split4(
    __half* __restrict__ hi, __half* __restrict__ lo, size_t off, float4 v)
{
    __half h0 = __float2half(v.x), h1 = __float2half(v.y);
    __half h2 = __float2half(v.z), h3 = __float2half(v.w);
    __half l0 = __float2half(v.x - __half2float(h0));
    __half l1 = __float2half(v.y - __half2float(h1));
    __half l2 = __float2half(v.z - __half2float(h2));
    __half l3 = __float2half(v.w - __half2float(h3));
    __half2 ph0, ph1, pl0, pl1;
    ph0.x = h0; ph0.y = h1; ph1.x = h2; ph1.y = h3;
    pl0.x = l0; pl0.y = l1; pl1.x = l2; pl1.y = l3;
    uint2 uh, ul;
    uh.x = *reinterpret_cast<uint32_t*>(&ph0);
    uh.y = *reinterpret_cast<uint32_t*>(&ph1);
    ul.x = *reinterpret_cast<uint32_t*>(&pl0);
    ul.y = *reinterpret_cast<uint32_t*>(&pl1);
    *reinterpret_cast<uint2*>(hi + off) = uh;
    *reinterpret_cast<uint2*>(lo + off) = ul;
}

static __device__ __forceinline__ void store_split2(
    __half* __restrict__ hi, __half* __restrict__ lo,
    size_t off, float x, float y)
{
    __half h0 = __float2half(x), h1 = __float2half(y);
    __half2 ph, pl;
    ph.x = h0; ph.y = h1;
    pl.x = __float2half(x - __half2float(h0));
    pl.y = __float2half(y - __half2float(h1));
    *reinterpret_cast<__half2*>(hi + off) = ph;
    *reinterpret_cast<__half2*>(lo + off) = pl;
}

static __device__ __forceinline__ uint32_t pack2h(float x, float y) {
    __half2 h;
    h.x = __float2half(x); h.y = __float2half(y);
    return *reinterpret_cast<uint32_t*>(&h);
}

// elementwise split: X[n] -> hi/lo
__global__ void __launch_bounds__(256) split_k(
    const float* __restrict__ X, __half* __restrict__ hi,
    __half* __restrict__ lo, int n4)
{
    int i = blockIdx.x * 256 + threadIdx.x;
    if (i < n4) {
        float4 v = reinterpret_cast<const float4*>(X)[i];
        store_split4(hi, lo, (size_t)i * 4, v);
    }
}

// transpose + convert: W[K,N] -> T[N,K] (single fp16, B-side operand)
__global__ void __launch_bounds__(256) tconv_k(
    const float* __restrict__ W, __half* __restrict__ T, int K, int N)
{
    __shared__ float t[32][33];
    const int n0 = blockIdx.x * 32, k0 = blockIdx.y * 32;
    const int tx = threadIdx.x, ty = threadIdx.y;   // (32, 8)
#pragma unroll
    for (int j = 0; j < 32; j += 8)
        t[ty + j][tx] = W[(size_t)(k0 + ty + j) * N + n0 + tx];
    __syncthreads();
#pragma unroll
    for (int j = 0; j < 32; j += 8)
        T[(size_t)(n0 + ty + j) * K + k0 + tx] = __float2half(t[tx][ty + j]);
}

// ---------------- mma.sync 2-term fp16 GEMM ---------------------------------
// C[M,N] = (Ahi+Alo)[M,K] @ Bh^T  (B single fp16, stored [N,K] row-major).
// CTA 128x128, 8 warps (warp tile 32x64), K-chunk 32, cp.async double buffer.
#define STG   30720
#define ALOFF 10240
#define BOFF  20480
#define TGEMM_SMEM (2 * STG)

static __device__ __forceinline__ void load_stage(
    uint32_t smb, int stage,
    const __half* __restrict__ Ah, const __half* __restrict__ Al,
    const __half* __restrict__ Bh,
    int rowBase, int colBase, int K, int kt, int tid)
{
    const uint32_t sb = smb + stage * STG;
#pragma unroll
    for (int i = 0; i < 2; i++) {
        int idx = tid + i * 256;         // 0..511
        int r = idx >> 2;                // 0..127
        int kb = (idx & 3) * 8;          // 0,8,16,24
        uint32_t so = sb + (uint32_t)(r * 80 + kb * 2);
        size_t ga = (size_t)(rowBase + r) * K + kt + kb;
        size_t gb = (size_t)(colBase + r) * K + kt + kb;
        CP16(so,         Ah + ga);
        CP16(so + ALOFF, Al + ga);
        CP16(so + BOFF,  Bh + gb);
    }
}

template <bool BIAS, bool RELU, bool RES, bool OSPLIT>
__global__ void __launch_bounds__(256, 2) tgemm_k(
    const __half* __restrict__ Ah, const __half* __restrict__ Al,
    const __half* __restrict__ Bh,
    const float* __restrict__ bias, const float* __restrict__ res,
    float* __restrict__ C, __half* __restrict__ Chi,
    __half* __restrict__ Clo, int N, int K)
{
    extern __shared__ char sm[];
    const uint32_t smb = s2u(sm);
    const int tid = threadIdx.x;
    const int wid = tid >> 5, lane = tid & 31;
    const int m_base = (wid & 3) * 32;
    const int n_base = (wid >> 2) * 64;
    const int rowBase = blockIdx.y * 128, colBase = blockIdx.x * 128;

    float acc[2][8][4];
#pragma unroll
    for (int mf = 0; mf < 2; mf++)
#pragma unroll
        for (int nf = 0; nf < 8; nf++)
#pragma unroll
            for (int j = 0; j < 4; j++) acc[mf][nf][j] = 0.f;

    const uint32_t aOff = (uint32_t)((m_base + (lane & 15)) * 80 + (lane >> 4) * 16);
    const int bRow = (lane & 7) + ((lane >> 4) & 1) * 8;
    const uint32_t bOff = (uint32_t)((n_base + bRow) * 80 + ((lane >> 3) & 1) * 16);

    const int NC = K / 32;
    load_stage(smb, 0, Ah, Al, Bh, rowBase, colBase, K, 0, tid);
    CP_COMMIT();

    for (int c = 0; c < NC; ++c) {
        if (c + 1 < NC) {
            load_stage(smb, (c + 1) & 1, Ah, Al, Bh,
                       rowBase, colBase, K, (c + 1) * 32, tid);
            CP_COMMIT();
            CP_WAIT1();
        } else {
            CP_WAIT0();
        }
        __syncthreads();

        const uint32_t sb = smb + (uint32_t)(c & 1) * STG;
#pragma unroll
        for (int ks = 0; ks < 2; ks++) {
            uint32_t ah[2][4], al[2][4];
#pragma unroll
            for (int mf = 0; mf < 2; mf++) {
                ldsm4(ah[mf], sb + aOff + (uint32_t)(mf * 16 * 80 + ks * 32));
                ldsm4(al[mf], sb + ALOFF + aOff + (uint32_t)(mf * 16 * 80 + ks * 32));
            }
#pragma unroll
            for (int nf = 0; nf < 4; nf++) {
                uint32_t bh4[4];
                ldsm4(bh4, sb + BOFF + bOff + (uint32_t)(nf * 16 * 80 + ks * 32));
#pragma unroll
                for (int mf = 0; mf < 2; mf++) {
                    mma16816(acc[mf][nf * 2],     ah[mf], bh4);
                    mma16816(acc[mf][nf * 2],     al[mf], bh4);
                    mma16816(acc[mf][nf * 2 + 1], ah[mf], bh4 + 2);
                    mma16816(acc[mf][nf * 2 + 1], al[mf], bh4 + 2);
                }
            }
        }
        __syncthreads();
    }

    const int group = lane >> 2, tig = lane & 3;
#pragma unroll
    for (int mf = 0; mf < 2; mf++) {
#pragma unroll
        for (int nf = 0; nf < 8; nf++) {
            const int c0 = colBase + n_base + nf * 8 + tig * 2;
            float bx = 0.f, by = 0.f;
            if (BIAS) {
                float2 bb = *reinterpret_cast<const float2*>(bias + c0);
                bx = bb.x; by = bb.y;
            }
#pragma unroll
            for (int half = 0; half < 2; half++) {
                const int r = rowBase + m_base + mf * 16 + group + half * 8;
                float ox = acc[mf][nf][half * 2 + 0];
                float oy = acc[mf][nf][half * 2 + 1];
                if (BIAS) { ox += bx; oy += by; }
                if (RES) {
                    float2 rr = *reinterpret_cast<const float2*>(
                        res + (size_t)r * N + c0);
                    ox += rr.x; oy += rr.y;
                }
                if (RELU) { ox = fmaxf(ox, 0.f); oy = fmaxf(oy, 0.f); }
                if (OSPLIT) {
                    store_split2(Chi, Clo, (size_t)r * N + c0, ox, oy);
                } else {
                    float2 o2; o2.x = ox; o2.y = oy;
                    *reinterpret_cast<float2*>(C + (size_t)r * N + c0) = o2;
                }
            }
        }
    }
}

// ---------------- tensor-core flash attention --------------------------------
// QK^T: Q 2-term (hi/lo), K 1-term.  PV: P 1-term fp16, V 1-term.
// smem (fp16, row stride 72 elems = 144 B):
//   Qh @ 0      Ql @ 18432   (128 x 72 each)
//   Kh @ 36864               (64 keys x 72)
//   Vth @ 46080              (64 d x 72, V transposed at fill)
#define QHB 0
#define QLB 18432
#define KHB 36864
#define VHB 46080
#define ATT_SMEM 55296

__global__ void __launch_bounds__(256, 2) attn_tc_k(
    const __half* __restrict__ Qh, const __half* __restrict__ Ql,
    const __half* __restrict__ Kh, const __half* __restrict__ Vh,
    __half* __restrict__ Ohi, __half* __restrict__ Olo)
{
    extern __shared__ char sm[];
    const uint32_t smb = s2u(sm);
    const int tid = threadIdx.x;
    const int wid = tid >> 5, lane = tid & 31;
    const int group = lane >> 2, tig = lane & 3;
    const int qBase = blockIdx.x * 128;
    const int h = blockIdx.y, b = blockIdx.z;
    const size_t gbase = (size_t)b * Sv * Dv + (size_t)h * DKv;

#pragma unroll
    for (int i = 0; i < 4; i++) {
        int idx = tid + i * 256;
        int r = idx >> 3;
        int c = (idx & 7) * 8;
        size_t g = gbase + (size_t)(qBase + r) * Dv + c;
        uint32_t so = (uint32_t)(r * 144 + c * 2);
        CP16(smb + QHB + so, Qh + g);
        CP16(smb + QLB + so, Ql + g);
    }
    CP_COMMIT();

    float m0 = -1e30f, m1 = -1e30f, l0 = 0.f, l1 = 0.f;
    float O[8][4];
#pragma unroll
    for (int nf = 0; nf < 8; nf++)
#pragma unroll
        for (int j = 0; j < 4; j++) O[nf][j] = 0.f;

    const uint32_t aOff = (uint32_t)((wid * 16 + (lane & 15)) * 144 + (lane >> 4) * 16);
    const int bRow = (lane & 7) + ((lane >> 4) & 1) * 8;
    const uint32_t bOff = (uint32_t)(bRow * 144 + ((lane >> 3) & 1) * 16);

    for (int kt = 0; kt < Sv; kt += 64) {
        __syncthreads();
        // K fill (hi only)
#pragma unroll
        for (int i = 0; i < 2; i++) {
            int r = (tid + i * 256) >> 3;
            int c = ((tid + i * 256) & 7) * 8;
            size_t g = gbase + (size_t)(kt + r) * Dv + c;
            CP16(smb + KHB + (uint32_t)(r * 144 + c * 2), Kh + g);
        }
        CP_COMMIT();
        // V fill TRANSPOSED (hi only)
#pragma unroll
        for (int i = 0; i < 2; i++) {
            int idx = tid + i * 256;
            int key = idx & 63;
            int db = (idx >> 6) * 8;
            size_t g = gbase + (size_t)(kt + key) * Dv + db;
            uint4 hv = *reinterpret_cast<const uint4*>(Vh + g);
            const __half* hp = reinterpret_cast<const __half*>(&hv);
#pragma unroll
            for (int j = 0; j < 8; j++) {
                uint32_t so = (uint32_t)((db + j) * 144 + key * 2);
                *reinterpret_cast<__half*>(sm + VHB + so) = hp[j];
            }
        }
        CP_WAIT0();
        __syncthreads();

        // ---- S = Q @ K^T ----
        float S[8][4];
#pragma unroll
        for (int nf = 0; nf < 8; nf++)
#pragma unroll
            for (int j = 0; j < 4; j++) S[nf][j] = 0.f;
#pragma unroll
        for (int ks = 0; ks < 4; ks++) {
            uint32_t ah4[4], al4[4];
            ldsm4(ah4, smb + QHB + aOff + (uint32_t)(ks * 32));
            ldsm4(al4, smb + QLB + aOff + (uint32_t)(ks * 32));
#pragma unroll
            for (int nf2 = 0; nf2 < 4; nf2++) {
                uint32_t bh4[4];
                ldsm4(bh4, smb + KHB + bOff + (uint32_t)(nf2 * 16 * 144 + ks * 32));
                mma16816(S[nf2 * 2],     ah4, bh4);
                mma16816(S[nf2 * 2],     al4, bh4);
                mma16816(S[nf2 * 2 + 1], ah4, bh4 + 2);
                mma16816(S[nf2 * 2 + 1], al4, bh4 + 2);
            }
        }

        // ---- online softmax ----
        float mx0 = -1e30f, mx1 = -1e30f;
#pragma unroll
        for (int nf = 0; nf < 8; nf++) {
            mx0 = fmaxf(mx0, fmaxf(S[nf][0], S[nf][1]));
            mx1 = fmaxf(mx1, fmaxf(S[nf][2], S[nf][3]));
        }
        mx0 = fmaxf(mx0, __shfl_xor_sync(0xffffffffu, mx0, 1));
        mx0 = fmaxf(mx0, __shfl_xor_sync(0xffffffffu, mx0, 2));
        mx1 = fmaxf(mx1, __shfl_xor_sync(0xffffffffu, mx1, 1));
        mx1 = fmaxf(mx1, __shfl_xor_sync(0xffffffffu, mx1, 2));
        const float mn0 = fmaxf(m0, mx0), mn1 = fmaxf(m1, mx1);
        const float cr0 = pexp(m0 - mn0), cr1 = pexp(m1 - mn1);
        m0 = mn0; m1 = mn1;
        float s0 = 0.f, s1 = 0.f;
#pragma unroll
        for (int nf = 0; nf < 8; nf++) {
            S[nf][0] = pexp(S[nf][0] - mn0);
            S[nf][1] = pexp(S[nf][1] - mn0);
            S[nf][2] = pexp(S[nf][2] - mn1);
            S[nf][3] = pexp(S[nf][3] - mn1);
            s0 += S[nf][0] + S[nf][1];
            s1 += S[nf][2] + S[nf][3];
        }
        s0 += __shfl_xor_sync(0xffffffffu, s0, 1);
        s0 += __shfl_xor_sync(0xffffffffu, s0, 2);
        s1 += __shfl_xor_sync(0xffffffffu, s1, 1);
        s1 += __shfl_xor_sync(0xffffffffu, s1, 2);
        l0 = l0 * cr0 + s0;
        l1 = l1 * cr1 + s1;
#pragma unroll
        for (int nf = 0; nf < 8; nf++) {
            O[nf][0] *= cr0; O[nf][1] *= cr0;
            O[nf][2] *= cr1; O[nf][3] *= cr1;
        }

        // ---- O += P @ V  (P single-term fp16) ----
#pragma unroll
        for (int kf = 0; kf < 4; kf++) {
            uint32_t aP[4];
            aP[0] = pack2h(S[2 * kf][0],     S[2 * kf][1]);
            aP[1] = pack2h(S[2 * kf][2],     S[2 * kf][3]);
            aP[2] = pack2h(S[2 * kf + 1][0], S[2 * kf + 1][1]);
            aP[3] = pack2h(S[2 * kf + 1][2], S[2 * kf + 1][3]);
#pragma unroll
            for (int nf2 = 0; nf2 < 4; nf2++) {
                uint32_t bvh[4];
                ldsm4(bvh, smb + VHB + bOff + (uint32_t)(nf2 * 16 * 144 + kf * 32));
                mma16816(O[nf2 * 2],     aP, bvh);
                mma16816(O[nf2 * 2 + 1], aP, bvh + 2);
            }
        }
    }

    const float inv0 = 1.f / l0, inv1 = 1.f / l1;
    const int r0 = qBase + wid * 16 + group;
#pragma unroll
    for (int nf = 0; nf < 8; nf++) {
        const int col = nf * 8 + tig * 2;
        size_t off0 = gbase + (size_t)r0 * Dv + col;
        size_t off1 = gbase + (size_t)(r0 + 8) * Dv + col;
        store_split2(Ohi, Olo, off0, O[nf][0] * inv0, O[nf][1] * inv0);
        store_split2(Ohi, Olo, off1, O[nf][2] * inv1, O[nf][3] * inv1);
    }
}

// ---------------- layernorm (ddof=1, scalar gamma/beta) ---------------------
template <bool SPLIT>
__global__ void __launch_bounds__(256) ln_k(
    const float* __restrict__ X, float* __restrict__ Y,
    __half* __restrict__ Yh, __half* __restrict__ Yl,
    const float* __restrict__ gamma, const float* __restrict__ beta)
{
    __shared__ float sh[64];
    const int row = blockIdx.x;
    const int tid = threadIdx.x;
    const float4 v = *reinterpret_cast<const float4*>(X + (size_t)row * Dv + tid * 4);
    float s = v.x + v.y + v.z + v.w;
    float sq = fmaf(v.x, v.x, fmaf(v.y, v.y, fmaf(v.z, v.z, v.w * v.w)));
#pragma unroll
    for (int d = 16; d > 0; d >>= 1) {
        s  += __shfl_xor_sync(0xffffffffu, s, d);
        sq += __shfl_xor_sync(0xffffffffu, sq, d);
    }
    const int w = tid >> 5, lane = tid & 31;
    if (lane == 0) { sh[w] = s; sh[32 + w] = sq; }
    __syncthreads();
    if (tid == 0) {
        float S = 0.f, SQ = 0.f;
        for (int i = 0; i < 8; i++) { S += sh[i]; SQ += sh[32 + i]; }
        sh[48] = S; sh[49] = SQ;
    }
    __syncthreads();
    const float S = sh[48], SQ = sh[49];
    const float mean = S * (1.f / 1024.f);
    const float var = (SQ - 1024.f * mean * mean) * (1.f / 1023.f);
    const float scale = gamma[0] / sqrtf(var + 1e-5f);
    const float be = beta[0];
    float4 ov;
    ov.x = (v.x - mean) * scale + be;
    ov.y = (v.y - mean) * scale + be;
    ov.z = (v.z - mean) * scale + be;
    ov.w = (v.w - mean) * scale + be;
    *reinterpret_cast<float4*>(Y + (size_t)row * Dv + tid * 4) = ov;
    if (SPLIT) store_split4(Yh, Yl, (size_t)row * Dv + tid * 4, ov);
}

// ---------------- launch ----------------------------------------------------
extern "C" void kernel_launch(void* const* d_in, const int* in_sizes, int n_in,
                              void* d_out, int out_size)
{
    (void)in_sizes; (void)n_in; (void)out_size;
    const float* x      = (const float*)d_in[0];
    const float* wq     = (const float*)d_in[2];
    const float* wk     = (const float*)d_in[3];
    const float* wv     = (const float*)d_in[4];
    const float* wo     = (const float*)d_in[5];
    const float* w1     = (const float*)d_in[6];
    const float* b1     = (const float*)d_in[7];
    const float* w2     = (const float*)d_in[8];
    const float* b2     = (const float*)d_in[9];
    const float* gamma1 = (const float*)d_in[10];
    const float* beta1  = (const float*)d_in[11];
    const float* gamma2 = (const float*)d_in[12];
    const float* beta2  = (const float*)d_in[13];
    float* out = (float*)d_out;

    float *x1, *y;
    __half *xh, *xl, *qh, *ql, *kh, *vh, *ah, *al, *x1h, *x1l, *hh, *hl;
    __half *wqh, *wkh, *wvh, *woh, *w1h, *w2h;
    cudaGetSymbolAddress((void**)&x1,  g_x1);
    cudaGetSymbolAddress((void**)&y,   g_y);
    cudaGetSymbolAddress((void**)&xh,  g_xh);
    cudaGetSymbolAddress((void**)&xl,  g_xl);
    cudaGetSymbolAddress((void**)&qh,  g_qh);
    cudaGetSymbolAddress((void**)&ql,  g_ql);
    cudaGetSymbolAddress((void**)&kh,  g_kh);
    cudaGetSymbolAddress((void**)&vh,  g_vh);
    cudaGetSymbolAddress((void**)&ah,  g_ah);
    cudaGetSymbolAddress((void**)&al,  g_al);
    cudaGetSymbolAddress((void**)&x1h, g_x1h);
    cudaGetSymbolAddress((void**)&x1l, g_x1l);
    cudaGetSymbolAddress((void**)&hh,  g_hh);
    cudaGetSymbolAddress((void**)&hl,  g_hl);
    cudaGetSymbolAddress((void**)&wqh, g_wqh);
    cudaGetSymbolAddress((void**)&wkh, g_wkh);
    cudaGetSymbolAddress((void**)&wvh, g_wvh);
    cudaGetSymbolAddress((void**)&woh, g_woh);
    cudaGetSymbolAddress((void**)&w1h, g_w1h);
    cudaGetSymbolAddress((void**)&w2h, g_w2h);

    // scratch lo-dumps for K/V projections (carved from g_hh, written later by FFN1)
    __half* scr1 = hh;
    __half* scr2 = hh + (size_t)Mv * Dv;

    cudaFuncSetAttribute(attn_tc_k, cudaFuncAttributeMaxDynamicSharedMemorySize, ATT_SMEM);
    cudaFuncSetAttribute(tgemm_k<false, false, false, true>,
                         cudaFuncAttributeMaxDynamicSharedMemorySize, TGEMM_SMEM);
    cudaFuncSetAttribute(tgemm_k<false, false, true, false>,
                         cudaFuncAttributeMaxDynamicSharedMemorySize, TGEMM_SMEM);
    cudaFuncSetAttribute(tgemm_k<true, true, false, true>,
                         cudaFuncAttributeMaxDynamicSharedMemorySize, TGEMM_SMEM);
    cudaFuncSetAttribute(tgemm_k<true, false, true, false>,
                         cudaFuncAttributeMaxDynamicSharedMemorySize, TGEMM_SMEM);

    const dim3 tb(32, 8);
    // weight transpose + convert (single fp16)
    tconv_k<<<dim3(Dv / 32, Dv / 32), tb>>>(wq, wqh, Dv, Dv);
    tconv_k<<<dim3(Dv / 32, Dv / 32), tb>>>(wk, wkh, Dv, Dv);
    tconv_k<<<dim3(Dv / 32, Dv / 32), tb>>>(wv, wvh, Dv, Dv);
    tconv_k<<<dim3(Dv / 32, Dv / 32), tb>>>(wo, woh, Dv, Dv);
    tconv_k<<<dim3(DFFv / 32, Dv / 32), tb>>>(w1, w1h, Dv, DFFv);
    tconv_k<<<dim3(Dv / 32, DFFv / 32), tb>>>(w2, w2h, DFFv, Dv);
    // x split
    split_k<<<(Mv * Dv / 4 + 255) / 256, 256>>>(x, xh, xl, Mv * Dv / 4);

    // QKV projections (Q keeps its lo; K/V dump lo to scratch)
    tgemm_k<false, false, false, true><<<dim3(8, 32), 256, TGEMM_SMEM>>>(
        xh, xl, wqh, nullptr, nullptr, nullptr, qh, ql, Dv, Dv);
    tgemm_k<false, false, false, true><<<dim3(8, 32), 256, TGEMM_SMEM>>>(
        xh, xl, wkh, nullptr, nullptr, nullptr, kh, scr1, Dv, Dv);
    tgemm_k<false, false, false, true><<<dim3(8, 32), 256, TGEMM_SMEM>>>(
        xh, xl, wvh, nullptr, nullptr, nullptr, vh, scr2, Dv, Dv);

    // tensor-core flash attention
    attn_tc_k<<<dim3(Sv / 128, Hv, Bv), 256, ATT_SMEM>>>(
        qh, ql, kh, vh, ah, al);

    // O projection + residual(x), LN1
    tgemm_k<false, false, true, false><<<dim3(8, 32), 256, TGEMM_SMEM>>>(
        ah, al, woh, nullptr, x, y, nullptr, nullptr, Dv, Dv);
    ln_k<true><<<Mv, 256>>>(y, x1, x1h, x1l, gamma1, beta1);

    // FFN1 (bias + relu) -> split fp16
    tgemm_k<true, true, false, true><<<dim3(32, 32), 256, TGEMM_SMEM>>>(
        x1h, x1l, w1h, b1, nullptr, nullptr, hh, hl, DFFv, Dv);
    // FFN2 (bias + residual x1), LN2
    tgemm_k<true, false, true, false><<<dim3(8, 32), 256, TGEMM_SMEM>>>(
        hh, hl, w2h, b2, x1, y, nullptr, nullptr, Dv, DFFv);
    ln_k<false><<<Mv, 256>>>(y, out, nullptr, nullptr, gamma2, beta2);
}

// round 16
// speedup vs baseline: 1.8599x; 1.2433x over previous
#include <cuda_runtime.h>
#include <cuda_fp16.h>
#include <cstdint>
#include <math.h>

#define Bv   2
#define Sv   2048
#define Dv   1024
#define Hv   16
#define DKv  64
#define DFFv 4096
#define Mv   (Bv * Sv)   // 4096 rows

// ---------------- scratch (device globals; no allocation allowed) ----------
__device__ float g_x1[Mv * Dv];
__device__ float g_y[Mv * Dv];

__device__ __half g_xh[Mv * Dv],  g_xl[Mv * Dv];
__device__ __half g_qh[Mv * Dv],  g_ql[Mv * Dv];
__device__ __half g_kh[Mv * Dv];
__device__ __half g_vh[Mv * Dv];
__device__ __half g_ah[Mv * Dv],  g_al[Mv * Dv];
__device__ __half g_x1h[Mv * Dv];
__device__ __half g_hh[(size_t)Mv * DFFv];

__device__ __half g_wqh[Dv * Dv];
__device__ __half g_wkh[Dv * Dv];
__device__ __half g_wvh[Dv * Dv];
__device__ __half g_woh[Dv * Dv];
__device__ __half g_w1h[Dv * DFFv];   // transposed: [DFF, D]
__device__ __half g_w2h[Dv * DFFv];   // transposed: [D, DFF]

// ---------------- PTX helpers (base sm_80+ only) ----------------------------
static __device__ __forceinline__ uint32_t s2u(const void* p) {
    uint32_t a;
    asm("{ .reg .u64 t; cvta.to.shared.u64 t, %1; cvt.u32.u64 %0, t; }"
        : "=r"(a) : "l"(p));
    return a;
}

static __device__ __forceinline__ void ldsm4(uint32_t* r, uint32_t addr) {
    asm volatile("ldmatrix.sync.aligned.m8n8.x4.shared.b16 {%0,%1,%2,%3}, [%4];"
        : "=r"(r[0]), "=r"(r[1]), "=r"(r[2]), "=r"(r[3]) : "r"(addr));
}

static __device__ __forceinline__ void mma16816(
    float* d, const uint32_t* a, const uint32_t* b)
{
    asm volatile("mma.sync.aligned.m16n8k16.row.col.f32.f16.f16.f32 "
        "{%0,%1,%2,%3}, {%4,%5,%6,%7}, {%8,%9}, {%0,%1,%2,%3};"
        : "+f"(d[0]), "+f"(d[1]), "+f"(d[2]), "+f"(d[3])
        : "r"(a[0]), "r"(a[1]), "r"(a[2]), "r"(a[3]), "r"(b[0]), "r"(b[1]));
}

#define CP16(dst, src) \
    asm volatile("cp.async.cg.shared.global [%0], [%1], 16;" \
                 :: "r"(dst), "l"(src))
#define CP_COMMIT() asm volatile("cp.async.commit_group;" ::: "memory")
#define CP_WAIT0()  asm volatile("cp.async.wait_group 0;" ::: "memory")
#define CP_WAIT1()  asm volatile("cp.async.wait_group 1;" ::: "memory")

// ---------------- fast exp on FMA pipe: pexp(s) = exp(s / 8) ----------------
static __device__ __forceinline__ float pexp(float s) {
    const float C = 0.125f * 1.4426950408889634f;
    s = fmaxf(s, -500.0f);
    float yr = fmaf(s, C, 12582912.0f);
    int   n  = __float_as_int(yr) - 0x4B400000;
    float nf = yr - 12582912.0f;
    float f  = fmaf(s, C, -nf);
    float p  = 0.0018775767f;
    p = fmaf(p, f, 0.0089893397f);
    p = fmaf(p, f, 0.0558026980f);
    p = fmaf(p, f, 0.2401597153f);
    p = fmaf(p, f, 0.6931471825f);
    p = fmaf(p, f, 1.0f);
    return __int_as_float(__float_as_int(p) + (n << 23));
}

// ---------------- fp16 hi/lo split helpers ----------------------------------
static __device__ __forceinline__ void store_split4(
    __half* __restrict__ hi, __half* __restrict__ lo, size_t off, float4 v)
{
    __half h0 = __float2half(v.x), h1 = __float2half(v.y);
    __half h2 = __float2half(v.z), h3 = __float2half(v.w);
    __half l0 = __float2half(v.x - __half2float(h0));
    __half l1 = __float2half(v.y - __half2float(h1));
    __half l2 = __float2half(v.z - __half2float(h2));
    __half l3 = __float2half(v.w - __half2float(h3));
    __half2 ph0, ph1, pl0, pl1;
    ph0.x = h0; ph0.y = h1; ph1.x = h2; ph1.y = h3;
    pl0.x = l0; pl0.y = l1; pl1.x = l2; pl1.y = l3;
    uint2 uh, ul;
    uh.x = *reinterpret_cast<uint32_t*>(&ph0);
    uh.y = *reinterpret_cast<uint32_t*>(&ph1);
    ul.x = *reinterpret_cast<uint32_t*>(&pl0);
    ul.y = *reinterpret_cast<uint32_t*>(&pl1);
    *reinterpret_cast<uint2*>(hi + off) = uh;
    *reinterpret_cast<uint2*>(lo + off) = ul;
}

static __device__ __forceinline__ void store_split2(
    __half* __restrict__ hi, __half* __restrict__ lo,
    size_t off, float x, float y)
{
    __half h0 = __float2half(x), h1 = __float2half(y);
    __half2 ph, pl;
    ph.x = h0; ph.y = h1;
    pl.x = __float2half(x - __half2float(h0));
    pl.y = __float2half(y - __half2float(h1));
    *reinterpret_cast<__half2*>(hi + off) = ph;
    *reinterpret_cast<__half2*>(lo + off) = pl;
}

static __device__ __forceinline__ uint32_t pack2h(float x, float y) {
    __half2 h;
    h.x = __float2half(x); h.y = __float2half(y);
    return *reinterpret_cast<uint32_t*>(&h);
}

// elementwise split: X[n] -> hi/lo
__global__ void __launch_bounds__(256) split_k(
    const float* __restrict__ X, __half* __restrict__ hi,
    __half* __restrict__ lo, int n4)
{
    int i = blockIdx.x * 256 + threadIdx.x;
    if (i < n4) {
        float4 v = reinterpret_cast<const float4*>(X)[i];
        store_split4(hi, lo, (size_t)i * 4, v);
    }
}

// transpose + convert: W[K,N] -> T[N,K] (single fp16, B-side operand)
__global__ void __launch_bounds__(256) tconv_k(
    const float* __restrict__ W, __half* __restrict__ T, int K, int N)
{
    __shared__ float t[32][33];
    const int n0 = blockIdx.x * 32, k0 = blockIdx.y * 32;
    const int tx = threadIdx.x, ty = threadIdx.y;   // (32, 8)
#pragma unroll
    for (int j = 0; j < 32; j += 8)
        t[ty + j][tx] = W[(size_t)(k0 + ty + j) * N + n0 + tx];
    __syncthreads();
#pragma unroll
    for (int j = 0; j < 32; j += 8)
        T[(size_t)(n0 + ty + j) * K + k0 + tx] = __float2half(t[tx][ty + j]);
}

// ---------------- mma.sync fp16 GEMM ----------------------------------------
// C[M,N] = A[M,K] @ Bh^T, A either 2-term (Ahi+Alo) or plain fp16 (ALO=false).
// B single fp16 stored [N,K] row-major. CTA 128x128, 8 warps (32x64 warp tile),
// K-chunk 32, cp.async double buffer.
// OMODE: 0 = fp32 out, 1 = split hi/lo fp16 out, 2 = plain fp16 out.
#define STG   30720
#define ALOFF 10240
#define BOFF  20480
#define TGEMM_SMEM (2 * STG)

template <bool ALO>
static __device__ __forceinline__ void load_stage(
    uint32_t smb, int stage,
    const __half* __restrict__ Ah, const __half* __restrict__ Al,
    const __half* __restrict__ Bh,
    int rowBase, int colBase, int K, int kt, int tid)
{
    const uint32_t sb = smb + stage * STG;
#pragma unroll
    for (int i = 0; i < 2; i++) {
        int idx = tid + i * 256;         // 0..511
        int r = idx >> 2;                // 0..127
        int kb = (idx & 3) * 8;          // 0,8,16,24
        uint32_t so = sb + (uint32_t)(r * 80 + kb * 2);
        size_t ga = (size_t)(rowBase + r) * K + kt + kb;
        size_t gb = (size_t)(colBase + r) * K + kt + kb;
        CP16(so, Ah + ga);
        if (ALO) CP16(so + ALOFF, Al + ga);
        CP16(so + BOFF, Bh + gb);
    }
}

template <bool ALO, bool BIAS, bool RELU, bool RES, int OMODE>
__global__ void __launch_bounds__(256, 2) tgemm_k(
    const __half* __restrict__ Ah, const __half* __restrict__ Al,
    const __half* __restrict__ Bh,
    const float* __restrict__ bias, const float* __restrict__ res,
    float* __restrict__ C, __half* __restrict__ Chi,
    __half* __restrict__ Clo, int N, int K)
{
    extern __shared__ char sm[];
    const uint32_t smb = s2u(sm);
    const int tid = threadIdx.x;
    const int wid = tid >> 5, lane = tid & 31;
    const int m_base = (wid & 3) * 32;
    const int n_base = (wid >> 2) * 64;
    const int rowBase = blockIdx.y * 128, colBase = blockIdx.x * 128;

    float acc[2][8][4];
#pragma unroll
    for (int mf = 0; mf < 2; mf++)
#pragma unroll
        for (int nf = 0; nf < 8; nf++)
#pragma unroll
            for (int j = 0; j < 4; j++) acc[mf][nf][j] = 0.f;

    const uint32_t aOff = (uint32_t)((m_base + (lane & 15)) * 80 + (lane >> 4) * 16);
    const int bRow = (lane & 7) + ((lane >> 4) & 1) * 8;
    const uint32_t bOff = (uint32_t)((n_base + bRow) * 80 + ((lane >> 3) & 1) * 16);

    const int NC = K / 32;
    load_stage<ALO>(smb, 0, Ah, Al, Bh, rowBase, colBase, K, 0, tid);
    CP_COMMIT();

    for (int c = 0; c < NC; ++c) {
        if (c + 1 < NC) {
            load_stage<ALO>(smb, (c + 1) & 1, Ah, Al, Bh,
                            rowBase, colBase, K, (c + 1) * 32, tid);
            CP_COMMIT();
            CP_WAIT1();
        } else {
            CP_WAIT0();
        }
        __syncthreads();

        const uint32_t sb = smb + (uint32_t)(c & 1) * STG;
#pragma unroll
        for (int ks = 0; ks < 2; ks++) {
            uint32_t ah[2][4], al[2][4];
#pragma unroll
            for (int mf = 0; mf < 2; mf++) {
                ldsm4(ah[mf], sb + aOff + (uint32_t)(mf * 16 * 80 + ks * 32));
                if (ALO)
                    ldsm4(al[mf], sb + ALOFF + aOff + (uint32_t)(mf * 16 * 80 + ks * 32));
            }
#pragma unroll
            for (int nf = 0; nf < 4; nf++) {
                uint32_t bh4[4];
                ldsm4(bh4, sb + BOFF + bOff + (uint32_t)(nf * 16 * 80 + ks * 32));
#pragma unroll
                for (int mf = 0; mf < 2; mf++) {
                    mma16816(acc[mf][nf * 2],     ah[mf], bh4);
                    if (ALO) mma16816(acc[mf][nf * 2], al[mf], bh4);
                    mma16816(acc[mf][nf * 2 + 1], ah[mf], bh4 + 2);
                    if (ALO) mma16816(acc[mf][nf * 2 + 1], al[mf], bh4 + 2);
                }
            }
        }
        __syncthreads();
    }

    const int group = lane >> 2, tig = lane & 3;
#pragma unroll
    for (int mf = 0; mf < 2; mf++) {
#pragma unroll
        for (int nf = 0; nf < 8; nf++) {
            const int c0 = colBase + n_base + nf * 8 + tig * 2;
            float bx = 0.f, by = 0.f;
            if (BIAS) {
                float2 bb = *reinterpret_cast<const float2*>(bias + c0);
                bx = bb.x; by = bb.y;
            }
#pragma unroll
            for (int half = 0; half < 2; half++) {
                const int r = rowBase + m_base + mf * 16 + group + half * 8;
                float ox = acc[mf][nf][half * 2 + 0];
                float oy = acc[mf][nf][half * 2 + 1];
                if (BIAS) { ox += bx; oy += by; }
                if (RES) {
                    float2 rr = *reinterpret_cast<const float2*>(
                        res + (size_t)r * N + c0);
                    ox += rr.x; oy += rr.y;
                }
                if (RELU) { ox = fmaxf(ox, 0.f); oy = fmaxf(oy, 0.f); }
                if (OMODE == 1) {
                    store_split2(Chi, Clo, (size_t)r * N + c0, ox, oy);
                } else if (OMODE == 2) {
                    *reinterpret_cast<uint32_t*>(Chi + (size_t)r * N + c0) =
                        pack2h(ox, oy);
                } else {
                    float2 o2; o2.x = ox; o2.y = oy;
                    *reinterpret_cast<float2*>(C + (size_t)r * N + c0) = o2;
                }
            }
        }
    }
}

// ---------------- tensor-core flash attention --------------------------------
// QK^T: Q 2-term (hi/lo), K 1-term.  PV: P 1-term fp16, V 1-term.
#define QHB 0
#define QLB 18432
#define KHB 36864
#define VHB 46080
#define ATT_SMEM 55296

__global__ void __launch_bounds__(256, 2) attn_tc_k(
    const __half* __restrict__ Qh, const __half* __restrict__ Ql,
    const __half* __restrict__ Kh, const __half* __restrict__ Vh,
    __half* __restrict__ Ohi, __half* __restrict__ Olo)
{
    extern __shared__ char sm[];
    const uint32_t smb = s2u(sm);
    const int tid = threadIdx.x;
    const int wid = tid >> 5, lane = tid & 31;
    const int group = lane >> 2, tig = lane & 3;
    const int qBase = blockIdx.x * 128;
    const int h = blockIdx.y, b = blockIdx.z;
    const size_t gbase = (size_t)b * Sv * Dv + (size_t)h * DKv;

#pragma unroll
    for (int i = 0; i < 4; i++) {
        int idx = tid + i * 256;
        int r = idx >> 3;
        int c = (idx & 7) * 8;
        size_t g = gbase + (size_t)(qBase + r) * Dv + c;
        uint32_t so = (uint32_t)(r * 144 + c * 2);
        CP16(smb + QHB + so, Qh + g);
        CP16(smb + QLB + so, Ql + g);
    }
    CP_COMMIT();

    float m0 = -1e30f, m1 = -1e30f, l0 = 0.f, l1 = 0.f;
    float O[8][4];
#pragma unroll
    for (int nf = 0; nf < 8; nf++)
#pragma unroll
        for (int j = 0; j < 4; j++) O[nf][j] = 0.f;

    const uint32_t aOff = (uint32_t)((wid * 16 + (lane & 15)) * 144 + (lane >> 4) * 16);
    const int bRow = (lane & 7) + ((lane >> 4) & 1) * 8;
    const uint32_t bOff = (uint32_t)(bRow * 144 + ((lane >> 3) & 1) * 16);

    for (int kt = 0; kt < Sv; kt += 64) {
        __syncthreads();
        // K fill (hi only)
#pragma unroll
        for (int i = 0; i < 2; i++) {
            int r = (tid + i * 256) >> 3;
            int c = ((tid + i * 256) & 7) * 8;
            size_t g = gbase + (size_t)(kt + r) * Dv + c;
            CP16(smb + KHB + (uint32_t)(r * 144 + c * 2), Kh + g);
        }
        CP_COMMIT();
        // V fill TRANSPOSED (hi only)
#pragma unroll
        for (int i = 0; i < 2; i++) {
            int idx = tid + i * 256;
            int key = idx & 63;
            int db = (idx >> 6) * 8;
            size_t g = gbase + (size_t)(kt + key) * Dv + db;
            uint4 hv = *reinterpret_cast<const uint4*>(Vh + g);
            const __half* hp = reinterpret_cast<const __half*>(&hv);
#pragma unroll
            for (int j = 0; j < 8; j++) {
                uint32_t so = (uint32_t)((db + j) * 144 + key * 2);
                *reinterpret_cast<__half*>(sm + VHB + so) = hp[j];
            }
        }
        CP_WAIT0();
        __syncthreads();

        // ---- S = Q @ K^T ----
        float S[8][4];
#pragma unroll
        for (int nf = 0; nf < 8; nf++)
#pragma unroll
            for (int j = 0; j < 4; j++) S[nf][j] = 0.f;
#pragma unroll
        for (int ks = 0; ks < 4; ks++) {
            uint32_t ah4[4], al4[4];
            ldsm4(ah4, smb + QHB + aOff + (uint32_t)(ks * 32));
            ldsm4(al4, smb + QLB + aOff + (uint32_t)(ks * 32));
#pragma unroll
            for (int nf2 = 0; nf2 < 4; nf2++) {
                uint32_t bh4[4];
                ldsm4(bh4, smb + KHB + bOff + (uint32_t)(nf2 * 16 * 144 + ks * 32));
                mma16816(S[nf2 * 2],     ah4, bh4);
                mma16816(S[nf2 * 2],     al4, bh4);
                mma16816(S[nf2 * 2 + 1], ah4, bh4 + 2);
                mma16816(S[nf2 * 2 + 1], al4, bh4 + 2);
            }
        }

        // ---- online softmax ----
        float mx0 = -1e30f, mx1 = -1e30f;
#pragma unroll
        for (int nf = 0; nf < 8; nf++) {
            mx0 = fmaxf(mx0, fmaxf(S[nf][0], S[nf][1]));
            mx1 = fmaxf(mx1, fmaxf(S[nf][2], S[nf][3]));
        }
        mx0 = fmaxf(mx0, __shfl_xor_sync(0xffffffffu, mx0, 1));
        mx0 = fmaxf(mx0, __shfl_xor_sync(0xffffffffu, mx0, 2));
        mx1 = fmaxf(mx1, __shfl_xor_sync(0xffffffffu, mx1, 1));
        mx1 = fmaxf(mx1, __shfl_xor_sync(0xffffffffu, mx1, 2));
        const float mn0 = fmaxf(m0, mx0), mn1 = fmaxf(m1, mx1);
        const float cr0 = pexp(m0 - mn0), cr1 = pexp(m1 - mn1);
        m0 = mn0; m1 = mn1;
        float s0 = 0.f, s1 = 0.f;
#pragma unroll
        for (int nf = 0; nf < 8; nf++) {
            S[nf][0] = pexp(S[nf][0] - mn0);
            S[nf][1] = pexp(S[nf][1] - mn0);
            S[nf][2] = pexp(S[nf][2] - mn1);
            S[nf][3] = pexp(S[nf][3] - mn1);
            s0 += S[nf][0] + S[nf][1];
            s1 += S[nf][2] + S[nf][3];
        }
        s0 += __shfl_xor_sync(0xffffffffu, s0, 1);
        s0 += __shfl_xor_sync(0xffffffffu, s0, 2);
        s1 += __shfl_xor_sync(0xffffffffu, s1, 1);
        s1 += __shfl_xor_sync(0xffffffffu, s1, 2);
        l0 = l0 * cr0 + s0;
        l1 = l1 * cr1 + s1;
#pragma unroll
        for (int nf = 0; nf < 8; nf++) {
            O[nf][0] *= cr0; O[nf][1] *= cr0;
            O[nf][2] *= cr1; O[nf][3] *= cr1;
        }

        // ---- O += P @ V  (P single-term fp16) ----
#pragma unroll
        for (int kf = 0; kf < 4; kf++) {
            uint32_t aP[4];
            aP[0] = pack2h(S[2 * kf][0],     S[2 * kf][1]);
            aP[1] = pack2h(S[2 * kf][2],     S[2 * kf][3]);
            aP[2] = pack2h(S[2 * kf + 1][0], S[2 * kf + 1][1]);
            aP[3] = pack2h(S[2 * kf + 1][2], S[2 * kf + 1][3]);
#pragma unroll
            for (int nf2 = 0; nf2 < 4; nf2++) {
                uint32_t bvh[4];
                ldsm4(bvh, smb + VHB + bOff + (uint32_t)(nf2 * 16 * 144 + kf * 32));
                mma16816(O[nf2 * 2],     aP, bvh);
                mma16816(O[nf2 * 2 + 1], aP, bvh + 2);
            }
        }
    }

    const float inv0 = 1.f / l0, inv1 = 1.f / l1;
    const int r0 = qBase + wid * 16 + group;
#pragma unroll
    for (int nf = 0; nf < 8; nf++) {
        const int col = nf * 8 + tig * 2;
        size_t off0 = gbase + (size_t)r0 * Dv + col;
        size_t off1 = gbase + (size_t)(r0 + 8) * Dv + col;
        store_split2(Ohi, Olo, off0, O[nf][0] * inv0, O[nf][1] * inv0);
        store_split2(Ohi, Olo, off1, O[nf][2] * inv1, O[nf][3] * inv1);
    }
}

// ---------------- layernorm (ddof=1, scalar gamma/beta) ---------------------
// CONV: additionally write plain-fp16 copy of the output (A operand for FFN1)
template <bool CONV>
__global__ void __launch_bounds__(256) ln_k(
    const float* __restrict__ X, float* __restrict__ Y,
    __half* __restrict__ Yh,
    const float* __restrict__ gamma, const float* __restrict__ beta)
{
    __shared__ float sh[64];
    const int row = blockIdx.x;
    const int tid = threadIdx.x;
    const float4 v = *reinterpret_cast<const float4*>(X + (size_t)row * Dv + tid * 4);
    float s = v.x + v.y + v.z + v.w;
    float sq = fmaf(v.x, v.x, fmaf(v.y, v.y, fmaf(v.z, v.z, v.w * v.w)));
#pragma unroll
    for (int d = 16; d > 0; d >>= 1) {
        s  += __shfl_xor_sync(0xffffffffu, s, d);
        sq += __shfl_xor_sync(0xffffffffu, sq, d);
    }
    const int w = tid >> 5, lane = tid & 31;
    if (lane == 0) { sh[w] = s; sh[32 + w] = sq; }
    __syncthreads();
    if (tid == 0) {
        float S = 0.f, SQ = 0.f;
        for (int i = 0; i < 8; i++) { S += sh[i]; SQ += sh[32 + i]; }
        sh[48] = S; sh[49] = SQ;
    }
    __syncthreads();
    const float S = sh[48], SQ = sh[49];
    const float mean = S * (1.f / 1024.f);
    const float var = (SQ - 1024.f * mean * mean) * (1.f / 1023.f);
    const float scale = gamma[0] / sqrtf(var + 1e-5f);
    const float be = beta[0];
    float4 ov;
    ov.x = (v.x - mean) * scale + be;
    ov.y = (v.y - mean) * scale + be;
    ov.z = (v.z - mean) * scale + be;
    ov.w = (v.w - mean) * scale + be;
    *reinterpret_cast<float4*>(Y + (size_t)row * Dv + tid * 4) = ov;
    if (CONV) {
        uint2 u;
        u.x = pack2h(ov.x, ov.y);
        u.y = pack2h(ov.z, ov.w);
        *reinterpret_cast<uint2*>(Yh + (size_t)row * Dv + tid * 4) = u;
    }
}

// ---------------- launch ----------------------------------------------------
extern "C" void kernel_launch(void* const* d_in, const int* in_sizes, int n_in,
                              void* d_out, int out_size)
{
    (void)in_sizes; (void)n_in; (void)out_size;
    const float* x      = (const float*)d_in[0];
    const float* wq     = (const float*)d_in[2];
    const float* wk     = (const float*)d_in[3];
    const float* wv     = (const float*)d_in[4];
    const float* wo     = (const float*)d_in[5];
    const float* w1     = (const float*)d_in[6];
    const float* b1     = (const float*)d_in[7];
    const float* w2     = (const float*)d_in[8];
    const float* b2     = (const float*)d_in[9];
    const float* gamma1 = (const float*)d_in[10];
    const float* beta1  = (const float*)d_in[11];
    const float* gamma2 = (const float*)d_in[12];
    const float* beta2  = (const float*)d_in[13];
    float* out = (float*)d_out;

    float *x1, *y;
    __half *xh, *xl, *qh, *ql, *kh, *vh, *ah, *al, *x1h, *hh;
    __half *wqh, *wkh, *wvh, *woh, *w1h, *w2h;
    cudaGetSymbolAddress((void**)&x1,  g_x1);
    cudaGetSymbolAddress((void**)&y,   g_y);
    cudaGetSymbolAddress((void**)&xh,  g_xh);
    cudaGetSymbolAddress((void**)&xl,  g_xl);
    cudaGetSymbolAddress((void**)&qh,  g_qh);
    cudaGetSymbolAddress((void**)&ql,  g_ql);
    cudaGetSymbolAddress((void**)&kh,  g_kh);
    cudaGetSymbolAddress((void**)&vh,  g_vh);
    cudaGetSymbolAddress((void**)&ah,  g_ah);
    cudaGetSymbolAddress((void**)&al,  g_al);
    cudaGetSymbolAddress((void**)&x1h, g_x1h);
    cudaGetSymbolAddress((void**)&hh,  g_hh);
    cudaGetSymbolAddress((void**)&wqh, g_wqh);
    cudaGetSymbolAddress((void**)&wkh, g_wkh);
    cudaGetSymbolAddress((void**)&wvh, g_wvh);
    cudaGetSymbolAddress((void**)&woh, g_woh);
    cudaGetSymbolAddress((void**)&w1h, g_w1h);
    cudaGetSymbolAddress((void**)&w2h, g_w2h);

    cudaFuncSetAttribute(attn_tc_k, cudaFuncAttributeMaxDynamicSharedMemorySize, ATT_SMEM);
    cudaFuncSetAttribute(tgemm_k<true, false, false, false, 1>,
                         cudaFuncAttributeMaxDynamicSharedMemorySize, TGEMM_SMEM);
    cudaFuncSetAttribute(tgemm_k<true, false, false, false, 2>,
                         cudaFuncAttributeMaxDynamicSharedMemorySize, TGEMM_SMEM);
    cudaFuncSetAttribute(tgemm_k<true, false, false, true, 0>,
                         cudaFuncAttributeMaxDynamicSharedMemorySize, TGEMM_SMEM);
    cudaFuncSetAttribute(tgemm_k<false, true, true, false, 2>,
                         cudaFuncAttributeMaxDynamicSharedMemorySize, TGEMM_SMEM);
    cudaFuncSetAttribute(tgemm_k<false, true, false, true, 0>,
                         cudaFuncAttributeMaxDynamicSharedMemorySize, TGEMM_SMEM);

    const dim3 tb(32, 8);
    // weight transpose + convert (single fp16)
    tconv_k<<<dim3(Dv / 32, Dv / 32), tb>>>(wq, wqh, Dv, Dv);
    tconv_k<<<dim3(Dv / 32, Dv / 32), tb>>>(wk, wkh, Dv, Dv);
    tconv_k<<<dim3(Dv / 32, Dv / 32), tb>>>(wv, wvh, Dv, Dv);
    tconv_k<<<dim3(Dv / 32, Dv / 32), tb>>>(wo, woh, Dv, Dv);
    tconv_k<<<dim3(DFFv / 32, Dv / 32), tb>>>(w1, w1h, Dv, DFFv);
    tconv_k<<<dim3(Dv / 32, DFFv / 32), tb>>>(w2, w2h, DFFv, Dv);
    // x split (2-term; feeds QKV projections which keep A hi/lo)
    split_k<<<(Mv * Dv / 4 + 255) / 256, 256>>>(x, xh, xl, Mv * Dv / 4);

    // QKV projections: Q split out (feeds QK 2-term); K, V plain fp16 out
    tgemm_k<true, false, false, false, 1><<<dim3(8, 32), 256, TGEMM_SMEM>>>(
        xh, xl, wqh, nullptr, nullptr, nullptr, qh, ql, Dv, Dv);
    tgemm_k<true, false, false, false, 2><<<dim3(8, 32), 256, TGEMM_SMEM>>>(
        xh, xl, wkh, nullptr, nullptr, nullptr, kh, nullptr, Dv, Dv);
    tgemm_k<true, false, false, false, 2><<<dim3(8, 32), 256, TGEMM_SMEM>>>(
        xh, xl, wvh, nullptr, nullptr, nullptr, vh, nullptr, Dv, Dv);

    // tensor-core flash attention (emits split hi/lo for O-proj 2-term A)
    attn_tc_k<<<dim3(Sv / 128, Hv, Bv), 256, ATT_SMEM>>>(
        qh, ql, kh, vh, ah, al);

    // O projection (A 2-term) + residual(x), LN1 (emits plain fp16 x1h)
    tgemm_k<true, false, false, true, 0><<<dim3(8, 32), 256, TGEMM_SMEM>>>(
        ah, al, woh, nullptr, x, y, nullptr, nullptr, Dv, Dv);
    ln_k<true><<<Mv, 256>>>(y, x1, x1h, gamma1, beta1);

    // FFN1 (A 1-term, bias + relu) -> plain fp16 h
    tgemm_k<false, true, true, false, 2><<<dim3(32, 32), 256, TGEMM_SMEM>>>(
        x1h, nullptr, w1h, b1, nullptr, nullptr, hh, nullptr, DFFv, Dv);
    // FFN2 (A 1-term, bias + residual x1), LN2
    tgemm_k<false, true, false, true, 0><<<dim3(8, 32), 256, TGEMM_SMEM>>>(
        hh, nullptr, w2h, b2, x1, y, nullptr, nullptr, Dv, DFFv);
    ln_k<false><<<Mv, 256>>>(y, out, nullptr, gamma2, beta2);
}